// round 3
// baseline (speedup 1.0000x reference)
#include <cuda_runtime.h>
#include <math.h>
#include <stdint.h>

#define B_ 8
#define N_ 2048
#define C_ 512
#define H_ 8
#define D_ 64
#define F_ 1536
#define M_ (B_*N_)

// Scratch (allocation-free rule: __device__ globals)
__device__ float g_Q[(size_t)B_*H_*N_*D_];
__device__ float g_K[(size_t)B_*H_*N_*D_];
__device__ float g_V[(size_t)B_*H_*N_*D_];
__device__ float g_ctx[(size_t)B_*N_*C_];

// ---------------------------------------------------------------------------
__device__ __forceinline__ float tf32r(float x) {
    float y;
    asm("cvt.rna.tf32.f32 %0, %1;" : "=f"(y) : "f"(x));
    return y;
}

__device__ __forceinline__ void mma_tf32(float* c, const uint32_t* a, const uint32_t* b) {
    asm volatile(
        "mma.sync.aligned.m16n8k8.row.col.f32.tf32.tf32.f32 "
        "{%0,%1,%2,%3},{%4,%5,%6,%7},{%8,%9},{%0,%1,%2,%3};\n"
        : "+f"(c[0]), "+f"(c[1]), "+f"(c[2]), "+f"(c[3])
        : "r"(a[0]), "r"(a[1]), "r"(a[2]), "r"(a[3]), "r"(b[0]), "r"(b[1]));
}

// ---------------------------------------------------------------------------
// GEMM kernels: CTA 128x128, k-step 32, double-buffered smem with register
// prefetch -> ONE __syncthreads per k-step. Buffer = As(128x36)+Bs(128x36).
// ---------------------------------------------------------------------------
#define GEMM_BUF_FLOATS 9216            // 2 * 128*36
#define GEMM_SMEM_BYTES (2*GEMM_BUF_FLOATS*4)

__global__ __launch_bounds__(256) void qkv_mma_kernel(
    const float* __restrict__ x, const float* __restrict__ Wqkv,
    const int* __restrict__ ncp)
{
    extern __shared__ float sm[];
    const int tid  = threadIdx.x;
    const int warp = tid >> 5, lane = tid & 31;
    const int g = lane >> 2, tg = lane & 3;
    const int wm = warp >> 1, wn = warp & 1;
    const int m0 = blockIdx.y * 128, f0 = blockIdx.x * 128;

    float acc[2][8][4] = {};
    const int lrow = tid >> 3;            // 0..31
    const int lcol = (tid & 7) * 4;       // 0..28

    float4 av[4], bv[4];
    // prologue: tile 0 -> regs -> buf0
    #pragma unroll
    for (int p = 0; p < 4; p++) {
        const int row = lrow + p*32;
        av[p] = *(const float4*)(x    + (size_t)(m0+row)*C_ + lcol);
        bv[p] = *(const float4*)(Wqkv + (size_t)(f0+row)*C_ + lcol);
    }
    {
        float* As = sm; float* Bs = sm + 4608;
        #pragma unroll
        for (int p = 0; p < 4; p++) {
            const int row = lrow + p*32;
            float* a = As + row*36 + lcol; float* b = Bs + row*36 + lcol;
            a[0]=tf32r(av[p].x); a[1]=tf32r(av[p].y); a[2]=tf32r(av[p].z); a[3]=tf32r(av[p].w);
            b[0]=tf32r(bv[p].x); b[1]=tf32r(bv[p].y); b[2]=tf32r(bv[p].z); b[3]=tf32r(bv[p].w);
        }
    }
    __syncthreads();

    for (int kb = 0; kb < 16; kb++) {
        if (kb < 15) {
            const int k0 = (kb+1)*32;
            #pragma unroll
            for (int p = 0; p < 4; p++) {
                const int row = lrow + p*32;
                av[p] = *(const float4*)(x    + (size_t)(m0+row)*C_ + k0 + lcol);
                bv[p] = *(const float4*)(Wqkv + (size_t)(f0+row)*C_ + k0 + lcol);
            }
        }
        const float* As = sm + (kb&1)*GEMM_BUF_FLOATS;
        const float* Bs = As + 4608;
        #pragma unroll
        for (int ks = 0; ks < 32; ks += 8) {
            uint32_t af[2][4];
            #pragma unroll
            for (int mt = 0; mt < 2; mt++) {
                const float* ap = As + (wm*32 + mt*16 + g)*36 + ks + tg;
                af[mt][0]=__float_as_uint(ap[0]);      af[mt][1]=__float_as_uint(ap[8*36]);
                af[mt][2]=__float_as_uint(ap[4]);      af[mt][3]=__float_as_uint(ap[8*36+4]);
            }
            uint32_t bf[8][2];
            #pragma unroll
            for (int nt = 0; nt < 8; nt++) {
                const float* bp2 = Bs + (wn*64 + nt*8 + g)*36 + ks + tg;
                bf[nt][0]=__float_as_uint(bp2[0]);     bf[nt][1]=__float_as_uint(bp2[4]);
            }
            #pragma unroll
            for (int mt = 0; mt < 2; mt++)
                #pragma unroll
                for (int nt = 0; nt < 8; nt++)
                    mma_tf32(acc[mt][nt], af[mt], bf[nt]);
        }
        if (kb < 15) {
            float* Ad = sm + ((kb+1)&1)*GEMM_BUF_FLOATS;
            float* Bd = Ad + 4608;
            #pragma unroll
            for (int p = 0; p < 4; p++) {
                const int row = lrow + p*32;
                float* a = Ad + row*36 + lcol; float* b = Bd + row*36 + lcol;
                a[0]=tf32r(av[p].x); a[1]=tf32r(av[p].y); a[2]=tf32r(av[p].z); a[3]=tf32r(av[p].w);
                b[0]=tf32r(bv[p].x); b[1]=tf32r(bv[p].y); b[2]=tf32r(bv[p].z); b[3]=tf32r(bv[p].w);
            }
        }
        __syncthreads();
    }

    const int nc = ncp ? *ncp : 1;
    #pragma unroll
    for (int mt = 0; mt < 2; mt++) {
        #pragma unroll
        for (int hh = 0; hh < 2; hh++) {
            const int m = m0 + wm*32 + mt*16 + hh*8 + g;
            const int b = m >> 11, n = m & 2047;
            #pragma unroll
            for (int nt = 0; nt < 8; nt++) {
                const int f = f0 + wn*64 + nt*8 + 2*tg;
                float v0 = acc[mt][nt][hh*2+0], v1 = acc[mt][nt][hh*2+1];
                const int s = f >> 9, rem = f & 511, hd = rem >> 6, d0 = rem & 63;
                if (s < 2 && n >= nc) {
                    const int pi = d0 >> 1;
                    const float invf = expf(-(float)pi * (9.210340371976184f/32.f));
                    float sn, cs;
                    sincosf((float)(n - nc) * invf, &sn, &cs);
                    const float e = v0, o = v1;
                    v0 = e*cs - o*sn;
                    v1 = e*sn + o*cs;
                }
                if (s == 0) { v0 *= 0.125f; v1 *= 0.125f; }
                float* dst = (s == 0) ? g_Q : (s == 1) ? g_K : g_V;
                *(float2*)(dst + ((((size_t)b*H_ + hd)*N_ + n)*D_ + d0)) = make_float2(v0, v1);
            }
        }
    }
}

__global__ __launch_bounds__(256) void proj_mma_kernel(
    const float* __restrict__ Wp, const float* __restrict__ bp,
    float* __restrict__ out)
{
    extern __shared__ float sm[];
    const int tid  = threadIdx.x;
    const int warp = tid >> 5, lane = tid & 31;
    const int g = lane >> 2, tg = lane & 3;
    const int wm = warp >> 1, wn = warp & 1;
    const int m0 = blockIdx.y * 128, f0 = blockIdx.x * 128;

    float acc[2][8][4] = {};
    const int lrow = tid >> 3;
    const int lcol = (tid & 7) * 4;

    float4 av[4], bv[4];
    #pragma unroll
    for (int p = 0; p < 4; p++) {
        const int row = lrow + p*32;
        av[p] = *(const float4*)(g_ctx + (size_t)(m0+row)*C_ + lcol);
        bv[p] = *(const float4*)(Wp    + (size_t)(f0+row)*C_ + lcol);
    }
    {
        float* As = sm; float* Bs = sm + 4608;
        #pragma unroll
        for (int p = 0; p < 4; p++) {
            const int row = lrow + p*32;
            float* a = As + row*36 + lcol; float* b = Bs + row*36 + lcol;
            a[0]=tf32r(av[p].x); a[1]=tf32r(av[p].y); a[2]=tf32r(av[p].z); a[3]=tf32r(av[p].w);
            b[0]=tf32r(bv[p].x); b[1]=tf32r(bv[p].y); b[2]=tf32r(bv[p].z); b[3]=tf32r(bv[p].w);
        }
    }
    __syncthreads();

    for (int kb = 0; kb < 16; kb++) {
        if (kb < 15) {
            const int k0 = (kb+1)*32;
            #pragma unroll
            for (int p = 0; p < 4; p++) {
                const int row = lrow + p*32;
                av[p] = *(const float4*)(g_ctx + (size_t)(m0+row)*C_ + k0 + lcol);
                bv[p] = *(const float4*)(Wp    + (size_t)(f0+row)*C_ + k0 + lcol);
            }
        }
        const float* As = sm + (kb&1)*GEMM_BUF_FLOATS;
        const float* Bs = As + 4608;
        #pragma unroll
        for (int ks = 0; ks < 32; ks += 8) {
            uint32_t af[2][4];
            #pragma unroll
            for (int mt = 0; mt < 2; mt++) {
                const float* ap = As + (wm*32 + mt*16 + g)*36 + ks + tg;
                af[mt][0]=__float_as_uint(ap[0]);      af[mt][1]=__float_as_uint(ap[8*36]);
                af[mt][2]=__float_as_uint(ap[4]);      af[mt][3]=__float_as_uint(ap[8*36+4]);
            }
            uint32_t bf[8][2];
            #pragma unroll
            for (int nt = 0; nt < 8; nt++) {
                const float* bp2 = Bs + (wn*64 + nt*8 + g)*36 + ks + tg;
                bf[nt][0]=__float_as_uint(bp2[0]);     bf[nt][1]=__float_as_uint(bp2[4]);
            }
            #pragma unroll
            for (int mt = 0; mt < 2; mt++)
                #pragma unroll
                for (int nt = 0; nt < 8; nt++)
                    mma_tf32(acc[mt][nt], af[mt], bf[nt]);
        }
        if (kb < 15) {
            float* Ad = sm + ((kb+1)&1)*GEMM_BUF_FLOATS;
            float* Bd = Ad + 4608;
            #pragma unroll
            for (int p = 0; p < 4; p++) {
                const int row = lrow + p*32;
                float* a = Ad + row*36 + lcol; float* b = Bd + row*36 + lcol;
                a[0]=tf32r(av[p].x); a[1]=tf32r(av[p].y); a[2]=tf32r(av[p].z); a[3]=tf32r(av[p].w);
                b[0]=tf32r(bv[p].x); b[1]=tf32r(bv[p].y); b[2]=tf32r(bv[p].z); b[3]=tf32r(bv[p].w);
            }
        }
        __syncthreads();
    }

    #pragma unroll
    for (int mt = 0; mt < 2; mt++) {
        #pragma unroll
        for (int hh = 0; hh < 2; hh++) {
            const int m = m0 + wm*32 + mt*16 + hh*8 + g;
            #pragma unroll
            for (int nt = 0; nt < 8; nt++) {
                const int f = f0 + wn*64 + nt*8 + 2*tg;
                *(float2*)(out + (size_t)m*C_ + f) =
                    make_float2(acc[mt][nt][hh*2+0] + __ldg(bp+f),
                                acc[mt][nt][hh*2+1] + __ldg(bp+f+1));
            }
        }
    }
}

// ---------------------------------------------------------------------------
// Flash attention: CTA = 128 queries x (b,h); 8 warps, each warp owns 16
// query rows x FULL 64-key width -> softmax is warp-local (quad shuffles,
// no smem, no syncs). Q lives in registers as A-frags. K/V double-buffered
// in smem with register prefetch -> ONE sync per key tile.
// P C-frag -> A-frag relayout via intra-quad shuffles.
// ---------------------------------------------------------------------------
#define KBUF 4352          // 64*68 floats
#define VBUF 4608          // 64*72 floats
#define ATTN_SMEM_BYTES ((2*KBUF + 2*VBUF)*4)
#define NT_ (N_/64)

__global__ __launch_bounds__(256) void attn_mma_kernel(const float* __restrict__ mask)
{
    extern __shared__ float sm[];
    float* Kb[2] = { sm,            sm + KBUF };
    float* Vb[2] = { sm + 2*KBUF,   sm + 2*KBUF + VBUF };

    const int tid  = threadIdx.x;
    const int warp = tid >> 5, lane = tid & 31;
    const int g = lane >> 2, tg = lane & 3;
    const int qb = blockIdx.x * 128;
    const int q0 = qb + warp * 16;
    const int bh = blockIdx.y, b = bh >> 3, h = bh & 7;
    const float* Qg = g_Q + (size_t)bh * N_ * D_;
    const float* Kg = g_K + (size_t)bh * N_ * D_;
    const float* Vg = g_V + (size_t)bh * N_ * D_;
    const float* mrow = mask + (size_t)b * N_;

    // Q as A-frags (resident): aq[ks] covers d = ks*8 .. ks*8+7
    uint32_t aq[8][4];
    #pragma unroll
    for (int ks = 0; ks < 8; ks++) {
        aq[ks][0] = __float_as_uint(tf32r(Qg[(size_t)(q0+g  )*D_ + ks*8 + tg    ]));
        aq[ks][1] = __float_as_uint(tf32r(Qg[(size_t)(q0+g+8)*D_ + ks*8 + tg    ]));
        aq[ks][2] = __float_as_uint(tf32r(Qg[(size_t)(q0+g  )*D_ + ks*8 + tg + 4]));
        aq[ks][3] = __float_as_uint(tf32r(Qg[(size_t)(q0+g+8)*D_ + ks*8 + tg + 4]));
    }

    const int lrow = tid >> 2;          // 0..63
    const int lc0  = (tid & 3) * 16;

    float4 kr[4], vr[4];
    #pragma unroll
    for (int u = 0; u < 4; u++) {
        kr[u] = *(const float4*)(Kg + (size_t)lrow*D_ + lc0 + u*4);
        vr[u] = *(const float4*)(Vg + (size_t)lrow*D_ + lc0 + u*4);
    }
    {
        float* kd = Kb[0] + lrow*68 + lc0;
        float* vd = Vb[0] + lrow*72 + lc0;
        #pragma unroll
        for (int u = 0; u < 4; u++) {
            kd[u*4+0]=tf32r(kr[u].x); kd[u*4+1]=tf32r(kr[u].y);
            kd[u*4+2]=tf32r(kr[u].z); kd[u*4+3]=tf32r(kr[u].w);
            vd[u*4+0]=tf32r(vr[u].x); vd[u*4+1]=tf32r(vr[u].y);
            vd[u*4+2]=tf32r(vr[u].z); vd[u*4+3]=tf32r(vr[u].w);
        }
    }
    __syncthreads();

    float O[8][4] = {};
    float rmax0 = -1e30f, rmax1 = -1e30f, rsum0 = 0.f, rsum1 = 0.f;

    for (int t = 0; t < NT_; t++) {
        // prefetch tile t+1 into regs (overlaps with mma below)
        if (t < NT_-1) {
            const size_t off = (size_t)(t+1)*64*D_;
            #pragma unroll
            for (int u = 0; u < 4; u++) {
                kr[u] = *(const float4*)(Kg + off + (size_t)lrow*D_ + lc0 + u*4);
                vr[u] = *(const float4*)(Vg + off + (size_t)lrow*D_ + lc0 + u*4);
            }
        }
        const float* K_ = Kb[t&1];
        const float* V_ = Vb[t&1];

        // ---- S = Q K^T : warp tile m16 x n64 ----
        float S[8][4] = {};
        #pragma unroll
        for (int ks = 0; ks < 8; ks++) {
            uint32_t bf[8][2];
            #pragma unroll
            for (int nt = 0; nt < 8; nt++) {
                const float* bp2 = K_ + (nt*8 + g)*68 + ks*8 + tg;
                bf[nt][0]=__float_as_uint(bp2[0]);  bf[nt][1]=__float_as_uint(bp2[4]);
            }
            #pragma unroll
            for (int nt = 0; nt < 8; nt++)
                mma_tf32(S[nt], aq[ks], bf[nt]);
        }

        // ---- + key mask; warp-local row max (quad reduce) ----
        const int k0 = t*64;
        float tmax0 = -1e30f, tmax1 = -1e30f;
        #pragma unroll
        for (int nt = 0; nt < 8; nt++) {
            const float mv0 = __ldg(mrow + k0 + nt*8 + 2*tg);
            const float mv1 = __ldg(mrow + k0 + nt*8 + 2*tg + 1);
            S[nt][0] += mv0; S[nt][1] += mv1; S[nt][2] += mv0; S[nt][3] += mv1;
            tmax0 = fmaxf(tmax0, fmaxf(S[nt][0], S[nt][1]));
            tmax1 = fmaxf(tmax1, fmaxf(S[nt][2], S[nt][3]));
        }
        tmax0 = fmaxf(tmax0, __shfl_xor_sync(0xffffffffu, tmax0, 1));
        tmax0 = fmaxf(tmax0, __shfl_xor_sync(0xffffffffu, tmax0, 2));
        tmax1 = fmaxf(tmax1, __shfl_xor_sync(0xffffffffu, tmax1, 1));
        tmax1 = fmaxf(tmax1, __shfl_xor_sync(0xffffffffu, tmax1, 2));

        const float nm0 = fmaxf(rmax0, tmax0), nm1 = fmaxf(rmax1, tmax1);
        const float fac0 = __expf(rmax0 - nm0), fac1 = __expf(rmax1 - nm1);
        rmax0 = nm0; rmax1 = nm1;

        // ---- P = exp(S - m), rounded to tf32; partial sums; O rescale ----
        uint32_t pc[8][4];
        float ts0 = 0.f, ts1 = 0.f;
        #pragma unroll
        for (int nt = 0; nt < 8; nt++) {
            const float p0 = __expf(S[nt][0] - nm0);
            const float p1 = __expf(S[nt][1] - nm0);
            const float p2 = __expf(S[nt][2] - nm1);
            const float p3 = __expf(S[nt][3] - nm1);
            ts0 += p0 + p1; ts1 += p2 + p3;
            pc[nt][0]=__float_as_uint(tf32r(p0)); pc[nt][1]=__float_as_uint(tf32r(p1));
            pc[nt][2]=__float_as_uint(tf32r(p2)); pc[nt][3]=__float_as_uint(tf32r(p3));
            O[nt][0] *= fac0; O[nt][1] *= fac0; O[nt][2] *= fac1; O[nt][3] *= fac1;
        }
        ts0 += __shfl_xor_sync(0xffffffffu, ts0, 1);
        ts0 += __shfl_xor_sync(0xffffffffu, ts0, 2);
        ts1 += __shfl_xor_sync(0xffffffffu, ts1, 1);
        ts1 += __shfl_xor_sync(0xffffffffu, ts1, 2);
        rsum0 = rsum0*fac0 + ts0;
        rsum1 = rsum1*fac1 + ts1;

        // ---- O += P V : per k-chunk, shuffle C-frag -> A-frag then mma ----
        const int base = lane & ~3;
        const int src1 = base | (tg >> 1);
        const int src2 = src1 + 2;
        const bool oddc = (tg & 1);
        #pragma unroll
        for (int kc = 0; kc < 8; kc++) {
            uint32_t pa[4];
            uint32_t v00 = __shfl_sync(0xffffffffu, pc[kc][0], src1);
            uint32_t v01 = __shfl_sync(0xffffffffu, pc[kc][1], src1);
            uint32_t v10 = __shfl_sync(0xffffffffu, pc[kc][2], src1);
            uint32_t v11 = __shfl_sync(0xffffffffu, pc[kc][3], src1);
            uint32_t w00 = __shfl_sync(0xffffffffu, pc[kc][0], src2);
            uint32_t w01 = __shfl_sync(0xffffffffu, pc[kc][1], src2);
            uint32_t w10 = __shfl_sync(0xffffffffu, pc[kc][2], src2);
            uint32_t w11 = __shfl_sync(0xffffffffu, pc[kc][3], src2);
            pa[0] = oddc ? v01 : v00;
            pa[1] = oddc ? v11 : v10;
            pa[2] = oddc ? w01 : w00;
            pa[3] = oddc ? w11 : w10;
            uint32_t bf[8][2];
            #pragma unroll
            for (int nt = 0; nt < 8; nt++) {
                const float* vp2 = V_ + (kc*8 + tg)*72 + nt*8 + g;
                bf[nt][0]=__float_as_uint(vp2[0]);  bf[nt][1]=__float_as_uint(vp2[4*72]);
            }
            #pragma unroll
            for (int nt = 0; nt < 8; nt++)
                mma_tf32(O[nt], pa, bf[nt]);
        }

        // ---- store prefetched tile into other buffer, single sync ----
        if (t < NT_-1) {
            float* kd = Kb[(t+1)&1] + lrow*68 + lc0;
            float* vd = Vb[(t+1)&1] + lrow*72 + lc0;
            #pragma unroll
            for (int u = 0; u < 4; u++) {
                kd[u*4+0]=tf32r(kr[u].x); kd[u*4+1]=tf32r(kr[u].y);
                kd[u*4+2]=tf32r(kr[u].z); kd[u*4+3]=tf32r(kr[u].w);
                vd[u*4+0]=tf32r(vr[u].x); vd[u*4+1]=tf32r(vr[u].y);
                vd[u*4+2]=tf32r(vr[u].z); vd[u*4+3]=tf32r(vr[u].w);
            }
        }
        __syncthreads();
    }

    // ---- normalize + write ctx [B, N, H*D] ----
    const float inv0 = 1.f / rsum0, inv1 = 1.f / rsum1;
    float* ctx0 = g_ctx + ((size_t)b*N_ + q0 + g    )*C_ + h*D_;
    float* ctx1 = g_ctx + ((size_t)b*N_ + q0 + g + 8)*C_ + h*D_;
    #pragma unroll
    for (int nt = 0; nt < 8; nt++) {
        const int d = nt*8 + 2*tg;
        *(float2*)(ctx0 + d) = make_float2(O[nt][0]*inv0, O[nt][1]*inv0);
        *(float2*)(ctx1 + d) = make_float2(O[nt][2]*inv1, O[nt][3]*inv1);
    }
}

// ---------------------------------------------------------------------------
extern "C" void kernel_launch(void* const* d_in, const int* in_sizes, int n_in,
                              void* d_out, int out_size)
{
    const float* x    = (const float*)d_in[0];
    const float* mask = (const float*)d_in[1];
    const float* Wqkv = (const float*)d_in[2];
    const float* Wp   = (const float*)d_in[3];
    const float* bp   = (const float*)d_in[4];
    const int*   ncp  = (n_in > 5) ? (const int*)d_in[5] : nullptr;

    cudaFuncSetAttribute(qkv_mma_kernel,
                         cudaFuncAttributeMaxDynamicSharedMemorySize, GEMM_SMEM_BYTES);
    cudaFuncSetAttribute(proj_mma_kernel,
                         cudaFuncAttributeMaxDynamicSharedMemorySize, GEMM_SMEM_BYTES);
    cudaFuncSetAttribute(attn_mma_kernel,
                         cudaFuncAttributeMaxDynamicSharedMemorySize, ATTN_SMEM_BYTES);

    qkv_mma_kernel <<<dim3(F_/128, M_/128), 256, GEMM_SMEM_BYTES>>>(x, Wqkv, ncp);
    attn_mma_kernel<<<dim3(N_/128, B_*H_), 256, ATTN_SMEM_BYTES>>>(mask);
    proj_mma_kernel<<<dim3(C_/128, M_/128), 256, GEMM_SMEM_BYTES>>>(Wp, bp, (float*)d_out);
}

// round 4
// speedup vs baseline: 1.2111x; 1.2111x over previous
#include <cuda_runtime.h>
#include <math.h>
#include <stdint.h>

#define B_ 8
#define N_ 2048
#define C_ 512
#define H_ 8
#define D_ 64
#define F_ 1536
#define M_ (B_*N_)

// Scratch (allocation-free rule: __device__ globals), all pre-rounded tf32
__device__ __align__(16) float g_Q[(size_t)B_*H_*N_*D_];
__device__ __align__(16) float g_K[(size_t)B_*H_*N_*D_];
__device__ __align__(16) float g_V[(size_t)B_*H_*N_*D_];
__device__ __align__(16) float g_ctx[(size_t)B_*N_*C_];
__device__ __align__(16) float g_xr[(size_t)M_*C_];
__device__ __align__(16) float g_Wq[(size_t)F_*C_];
__device__ __align__(16) float g_Wp[(size_t)C_*C_];

// ---------------------------------------------------------------------------
__device__ __forceinline__ float tf32r(float x) {
    float y;
    asm("cvt.rna.tf32.f32 %0, %1;" : "=f"(y) : "f"(x));
    return y;
}
__device__ __forceinline__ void mma_tf32(float* c, const uint32_t* a, const uint32_t* b) {
    asm volatile(
        "mma.sync.aligned.m16n8k8.row.col.f32.tf32.tf32.f32 "
        "{%0,%1,%2,%3},{%4,%5,%6,%7},{%8,%9},{%0,%1,%2,%3};\n"
        : "+f"(c[0]), "+f"(c[1]), "+f"(c[2]), "+f"(c[3])
        : "r"(a[0]), "r"(a[1]), "r"(a[2]), "r"(a[3]), "r"(b[0]), "r"(b[1]));
}
__device__ __forceinline__ void cpa16(uint32_t d, const float* s) {
    asm volatile("cp.async.cg.shared.global [%0], [%1], 16;" :: "r"(d), "l"(s));
}
__device__ __forceinline__ void cpa_commit() { asm volatile("cp.async.commit_group;"); }
#define CPA_WAIT1 asm volatile("cp.async.wait_group 1;")
#define CPA_WAIT0 asm volatile("cp.async.wait_group 0;")

// ---------------------------------------------------------------------------
// Kernel 0: round x, W_qkv, W_proj to tf32 once.
// ---------------------------------------------------------------------------
#define X4_  (M_*C_/4)          // 2097152
#define WQ4_ (F_*C_/4)          // 196608
#define WP4_ (C_*C_/4)          // 65536
__global__ __launch_bounds__(256) void round_pre(
    const float* __restrict__ x, const float* __restrict__ wq,
    const float* __restrict__ wp)
{
    int i = blockIdx.x * 256 + threadIdx.x;
    const int total = X4_ + WQ4_ + WP4_;
    for (; i < total; i += gridDim.x * 256) {
        const float4* src; float4* dst; int j;
        if (i < X4_)            { src = (const float4*)x;  dst = (float4*)g_xr; j = i; }
        else if (i < X4_+WQ4_)  { src = (const float4*)wq; dst = (float4*)g_Wq; j = i - X4_; }
        else                    { src = (const float4*)wp; dst = (float4*)g_Wp; j = i - X4_ - WQ4_; }
        float4 v = src[j];
        dst[j] = make_float4(tf32r(v.x), tf32r(v.y), tf32r(v.z), tf32r(v.w));
    }
}

// ---------------------------------------------------------------------------
// GEMM tile loader: 128x32 A + 128x32 B per stage, stride 36, cp.async 16B.
// ---------------------------------------------------------------------------
#define GSTG 9216                       // floats per stage (4608 A + 4608 B)
#define GEMM_SMEM_BYTES (3*GSTG*4)      // 110592
__device__ __forceinline__ void gemm_issue(uint32_t smb, const float* A, const float* Bm,
                                           int m0, int f0, int lrow, int lcol, int kb, int st)
{
    const float* xa = A  + (size_t)(m0+lrow)*C_ + kb*32 + lcol;
    const float* wb = Bm + (size_t)(f0+lrow)*C_ + kb*32 + lcol;
    uint32_t da = smb + (uint32_t)(st*GSTG + lrow*36 + lcol)*4u;
    uint32_t db = da + 4608u*4u;
    #pragma unroll
    for (int p = 0; p < 4; p++) {
        cpa16(da + p*(32*36*4), xa + (size_t)p*32*C_);
        cpa16(db + p*(32*36*4), wb + (size_t)p*32*C_);
    }
    cpa_commit();
}

// ---------------------------------------------------------------------------
// Kernel 1: qkv = xr @ Wq^T, fused RoPE (+scale Q), outputs rounded to tf32.
// ---------------------------------------------------------------------------
__global__ __launch_bounds__(256) void qkv_mma_kernel(const int* __restrict__ ncp)
{
    extern __shared__ float sm[];
    const uint32_t smb = (uint32_t)__cvta_generic_to_shared(sm);
    const int tid  = threadIdx.x;
    const int warp = tid >> 5, lane = tid & 31;
    const int g = lane >> 2, tg = lane & 3;
    const int wm = warp >> 1, wn = warp & 1;
    const int m0 = blockIdx.y * 128, f0 = blockIdx.x * 128;
    const int lrow = tid >> 3, lcol = (tid & 7) * 4;

    float acc[2][8][4] = {};

    gemm_issue(smb, g_xr, g_Wq, m0, f0, lrow, lcol, 0, 0);
    gemm_issue(smb, g_xr, g_Wq, m0, f0, lrow, lcol, 1, 1);

    for (int kb = 0; kb < 16; kb++) {
        if (kb < 15) { CPA_WAIT1; } else { CPA_WAIT0; }
        __syncthreads();
        if (kb + 2 < 16) gemm_issue(smb, g_xr, g_Wq, m0, f0, lrow, lcol, kb+2, (kb+2)%3);

        const float* As = sm + (kb%3)*GSTG;
        const float* Bs = As + 4608;
        #pragma unroll
        for (int ks = 0; ks < 32; ks += 8) {
            uint32_t af[2][4];
            #pragma unroll
            for (int mt = 0; mt < 2; mt++) {
                const float* ap = As + (wm*32 + mt*16 + g)*36 + ks + tg;
                af[mt][0]=__float_as_uint(ap[0]);   af[mt][1]=__float_as_uint(ap[8*36]);
                af[mt][2]=__float_as_uint(ap[4]);   af[mt][3]=__float_as_uint(ap[8*36+4]);
            }
            uint32_t bf[8][2];
            #pragma unroll
            for (int nt = 0; nt < 8; nt++) {
                const float* bp2 = Bs + (wn*64 + nt*8 + g)*36 + ks + tg;
                bf[nt][0]=__float_as_uint(bp2[0]);  bf[nt][1]=__float_as_uint(bp2[4]);
            }
            #pragma unroll
            for (int mt = 0; mt < 2; mt++)
                #pragma unroll
                for (int nt = 0; nt < 8; nt++)
                    mma_tf32(acc[mt][nt], af[mt], bf[nt]);
        }
    }

    const int nc = ncp ? *ncp : 1;
    #pragma unroll
    for (int mt = 0; mt < 2; mt++) {
        #pragma unroll
        for (int hh = 0; hh < 2; hh++) {
            const int m = m0 + wm*32 + mt*16 + hh*8 + g;
            const int b = m >> 11, n = m & 2047;
            #pragma unroll
            for (int nt = 0; nt < 8; nt++) {
                const int f = f0 + wn*64 + nt*8 + 2*tg;
                float v0 = acc[mt][nt][hh*2+0], v1 = acc[mt][nt][hh*2+1];
                const int s = f >> 9, rem = f & 511, hd = rem >> 6, d0 = rem & 63;
                if (s < 2 && n >= nc) {
                    const int pi = d0 >> 1;
                    const float invf = expf(-(float)pi * (9.210340371976184f/32.f));
                    float sn, cs;
                    sincosf((float)(n - nc) * invf, &sn, &cs);
                    const float e = v0, o = v1;
                    v0 = e*cs - o*sn;
                    v1 = e*sn + o*cs;
                }
                v0 = tf32r(v0); v1 = tf32r(v1);         // pre-round for attention
                if (s == 0) { v0 *= 0.125f; v1 *= 0.125f; }   // exact pow2
                float* dst = (s == 0) ? g_Q : (s == 1) ? g_K : g_V;
                *(float2*)(dst + ((((size_t)b*H_ + hd)*N_ + n)*D_ + d0)) = make_float2(v0, v1);
            }
        }
    }
}

// ---------------------------------------------------------------------------
// Kernel 2: flash attention. CTA = 128 q x (b,h); warp = 16 q x full 64 keys.
// Softmax fully warp-local. P round-trips via WARP-PRIVATE smem (syncwarp
// only). K/V via 3-stage cp.async, ONE __syncthreads per key tile.
// ---------------------------------------------------------------------------
#define KTILE 4352            // 64*68
#define VTILE 4608            // 64*72
#define ASTG  (KTILE+VTILE)   // 8960
#define POFF  (3*ASTG)        // 26880
#define ATTN_SMEM_BYTES ((3*ASTG + 8*16*68)*4)   // 142336
#define NT_ (N_/64)

__device__ __forceinline__ void attn_issue(uint32_t smb, const float* Kg, const float* Vg,
                                           int lrow, int lc0, int t, int st)
{
    const float* ksrc = Kg + (size_t)t*64*D_ + (size_t)lrow*D_ + lc0;
    const float* vsrc = Vg + (size_t)t*64*D_ + (size_t)lrow*D_ + lc0;
    uint32_t kd = smb + (uint32_t)(st*ASTG + lrow*68 + lc0)*4u;
    uint32_t vd = smb + (uint32_t)(st*ASTG + KTILE + lrow*72 + lc0)*4u;
    #pragma unroll
    for (int u = 0; u < 4; u++) {
        cpa16(kd + u*16, ksrc + u*4);
        cpa16(vd + u*16, vsrc + u*4);
    }
    cpa_commit();
}

__global__ __launch_bounds__(256) void attn_mma_kernel(const float* __restrict__ mask)
{
    extern __shared__ float sm[];
    const uint32_t smb = (uint32_t)__cvta_generic_to_shared(sm);
    const int tid  = threadIdx.x;
    const int warp = tid >> 5, lane = tid & 31;
    const int g = lane >> 2, tg = lane & 3;
    const int qb = blockIdx.x * 128;
    const int q0 = qb + warp * 16;
    const int bh = blockIdx.y, b = bh >> 3, h = bh & 7;
    const float* Qg = g_Q + (size_t)bh * N_ * D_;
    const float* Kg = g_K + (size_t)bh * N_ * D_;
    const float* Vg = g_V + (size_t)bh * N_ * D_;
    const float* mrow = mask + (size_t)b * N_;

    // Q A-frags resident (already tf32-rounded in gmem)
    uint32_t aq[8][4];
    #pragma unroll
    for (int ks = 0; ks < 8; ks++) {
        aq[ks][0] = __float_as_uint(Qg[(size_t)(q0+g  )*D_ + ks*8 + tg    ]);
        aq[ks][1] = __float_as_uint(Qg[(size_t)(q0+g+8)*D_ + ks*8 + tg    ]);
        aq[ks][2] = __float_as_uint(Qg[(size_t)(q0+g  )*D_ + ks*8 + tg + 4]);
        aq[ks][3] = __float_as_uint(Qg[(size_t)(q0+g+8)*D_ + ks*8 + tg + 4]);
    }

    const int lrow = tid >> 2, lc0 = (tid & 3) * 16;
    attn_issue(smb, Kg, Vg, lrow, lc0, 0, 0);
    attn_issue(smb, Kg, Vg, lrow, lc0, 1, 1);

    float* Pw = sm + POFF + warp * (16*68);      // warp-private P region

    float O[8][4] = {};
    float rmax0 = -1e30f, rmax1 = -1e30f, rsum0 = 0.f, rsum1 = 0.f;

    for (int t = 0; t < NT_; t++) {
        if (t < NT_-1) { CPA_WAIT1; } else { CPA_WAIT0; }
        __syncthreads();
        if (t + 2 < NT_) attn_issue(smb, Kg, Vg, lrow, lc0, t+2, (t+2)%3);

        const float* K_ = sm + (t%3)*ASTG;
        const float* V_ = K_ + KTILE;

        // ---- S = Q K^T : m16 x n64 ----
        float S[8][4] = {};
        #pragma unroll
        for (int ks = 0; ks < 8; ks++) {
            uint32_t bf[8][2];
            #pragma unroll
            for (int nt = 0; nt < 8; nt++) {
                const float* bp2 = K_ + (nt*8 + g)*68 + ks*8 + tg;
                bf[nt][0]=__float_as_uint(bp2[0]);  bf[nt][1]=__float_as_uint(bp2[4]);
            }
            #pragma unroll
            for (int nt = 0; nt < 8; nt++)
                mma_tf32(S[nt], aq[ks], bf[nt]);
        }

        // ---- + key mask; warp-local row max ----
        const int k0 = t*64;
        float tmax0 = -1e30f, tmax1 = -1e30f;
        #pragma unroll
        for (int nt = 0; nt < 8; nt++) {
            const float mv0 = __ldg(mrow + k0 + nt*8 + 2*tg);
            const float mv1 = __ldg(mrow + k0 + nt*8 + 2*tg + 1);
            S[nt][0] += mv0; S[nt][1] += mv1; S[nt][2] += mv0; S[nt][3] += mv1;
            tmax0 = fmaxf(tmax0, fmaxf(S[nt][0], S[nt][1]));
            tmax1 = fmaxf(tmax1, fmaxf(S[nt][2], S[nt][3]));
        }
        tmax0 = fmaxf(tmax0, __shfl_xor_sync(0xffffffffu, tmax0, 1));
        tmax0 = fmaxf(tmax0, __shfl_xor_sync(0xffffffffu, tmax0, 2));
        tmax1 = fmaxf(tmax1, __shfl_xor_sync(0xffffffffu, tmax1, 1));
        tmax1 = fmaxf(tmax1, __shfl_xor_sync(0xffffffffu, tmax1, 2));

        const float nm0 = fmaxf(rmax0, tmax0), nm1 = fmaxf(rmax1, tmax1);
        const float fac0 = __expf(rmax0 - nm0), fac1 = __expf(rmax1 - nm1);
        rmax0 = nm0; rmax1 = nm1;

        // ---- P = exp(S - m) -> warp-private smem (tf32); sums; O rescale ----
        float ts0 = 0.f, ts1 = 0.f;
        #pragma unroll
        for (int nt = 0; nt < 8; nt++) {
            const float p0 = __expf(S[nt][0] - nm0);
            const float p1 = __expf(S[nt][1] - nm0);
            const float p2 = __expf(S[nt][2] - nm1);
            const float p3 = __expf(S[nt][3] - nm1);
            ts0 += p0 + p1; ts1 += p2 + p3;
            *(float2*)&Pw[(g  )*68 + nt*8 + 2*tg] = make_float2(tf32r(p0), tf32r(p1));
            *(float2*)&Pw[(g+8)*68 + nt*8 + 2*tg] = make_float2(tf32r(p2), tf32r(p3));
            O[nt][0] *= fac0; O[nt][1] *= fac0; O[nt][2] *= fac1; O[nt][3] *= fac1;
        }
        ts0 += __shfl_xor_sync(0xffffffffu, ts0, 1);
        ts0 += __shfl_xor_sync(0xffffffffu, ts0, 2);
        ts1 += __shfl_xor_sync(0xffffffffu, ts1, 1);
        ts1 += __shfl_xor_sync(0xffffffffu, ts1, 2);
        rsum0 = rsum0*fac0 + ts0;
        rsum1 = rsum1*fac1 + ts1;
        __syncwarp();            // P visible warp-wide (warp-private region)

        // ---- O += P V ----
        #pragma unroll
        for (int kc = 0; kc < 8; kc++) {
            uint32_t pa[4];
            pa[0] = __float_as_uint(Pw[(g  )*68 + kc*8 + tg    ]);
            pa[1] = __float_as_uint(Pw[(g+8)*68 + kc*8 + tg    ]);
            pa[2] = __float_as_uint(Pw[(g  )*68 + kc*8 + tg + 4]);
            pa[3] = __float_as_uint(Pw[(g+8)*68 + kc*8 + tg + 4]);
            uint32_t bf[8][2];
            #pragma unroll
            for (int nt = 0; nt < 8; nt++) {
                const float* vp2 = V_ + (kc*8 + tg)*72 + nt*8 + g;
                bf[nt][0]=__float_as_uint(vp2[0]);  bf[nt][1]=__float_as_uint(vp2[4*72]);
            }
            #pragma unroll
            for (int nt = 0; nt < 8; nt++)
                mma_tf32(O[nt], pa, bf[nt]);
        }
        __syncwarp();            // P reads done before next tile overwrites
    }

    // ---- normalize + write ctx [B, N, H*D], rounded for proj cp.async ----
    const float inv0 = 1.f / rsum0, inv1 = 1.f / rsum1;
    float* ctx0 = g_ctx + ((size_t)b*N_ + q0 + g    )*C_ + h*D_;
    float* ctx1 = g_ctx + ((size_t)b*N_ + q0 + g + 8)*C_ + h*D_;
    #pragma unroll
    for (int nt = 0; nt < 8; nt++) {
        const int d = nt*8 + 2*tg;
        *(float2*)(ctx0 + d) = make_float2(tf32r(O[nt][0]*inv0), tf32r(O[nt][1]*inv0));
        *(float2*)(ctx1 + d) = make_float2(tf32r(O[nt][2]*inv1), tf32r(O[nt][3]*inv1));
    }
}

// ---------------------------------------------------------------------------
// Kernel 3: out = ctx @ Wp^T + b_proj
// ---------------------------------------------------------------------------
__global__ __launch_bounds__(256) void proj_mma_kernel(
    const float* __restrict__ bp, float* __restrict__ out)
{
    extern __shared__ float sm[];
    const uint32_t smb = (uint32_t)__cvta_generic_to_shared(sm);
    const int tid  = threadIdx.x;
    const int warp = tid >> 5, lane = tid & 31;
    const int g = lane >> 2, tg = lane & 3;
    const int wm = warp >> 1, wn = warp & 1;
    const int m0 = blockIdx.y * 128, f0 = blockIdx.x * 128;
    const int lrow = tid >> 3, lcol = (tid & 7) * 4;

    float acc[2][8][4] = {};

    gemm_issue(smb, g_ctx, g_Wp, m0, f0, lrow, lcol, 0, 0);
    gemm_issue(smb, g_ctx, g_Wp, m0, f0, lrow, lcol, 1, 1);

    for (int kb = 0; kb < 16; kb++) {
        if (kb < 15) { CPA_WAIT1; } else { CPA_WAIT0; }
        __syncthreads();
        if (kb + 2 < 16) gemm_issue(smb, g_ctx, g_Wp, m0, f0, lrow, lcol, kb+2, (kb+2)%3);

        const float* As = sm + (kb%3)*GSTG;
        const float* Bs = As + 4608;
        #pragma unroll
        for (int ks = 0; ks < 32; ks += 8) {
            uint32_t af[2][4];
            #pragma unroll
            for (int mt = 0; mt < 2; mt++) {
                const float* ap = As + (wm*32 + mt*16 + g)*36 + ks + tg;
                af[mt][0]=__float_as_uint(ap[0]);   af[mt][1]=__float_as_uint(ap[8*36]);
                af[mt][2]=__float_as_uint(ap[4]);   af[mt][3]=__float_as_uint(ap[8*36+4]);
            }
            uint32_t bf[8][2];
            #pragma unroll
            for (int nt = 0; nt < 8; nt++) {
                const float* bp2 = Bs + (wn*64 + nt*8 + g)*36 + ks + tg;
                bf[nt][0]=__float_as_uint(bp2[0]);  bf[nt][1]=__float_as_uint(bp2[4]);
            }
            #pragma unroll
            for (int mt = 0; mt < 2; mt++)
                #pragma unroll
                for (int nt = 0; nt < 8; nt++)
                    mma_tf32(acc[mt][nt], af[mt], bf[nt]);
        }
    }

    #pragma unroll
    for (int mt = 0; mt < 2; mt++) {
        #pragma unroll
        for (int hh = 0; hh < 2; hh++) {
            const int m = m0 + wm*32 + mt*16 + hh*8 + g;
            #pragma unroll
            for (int nt = 0; nt < 8; nt++) {
                const int f = f0 + wn*64 + nt*8 + 2*tg;
                *(float2*)(out + (size_t)m*C_ + f) =
                    make_float2(acc[mt][nt][hh*2+0] + __ldg(bp+f),
                                acc[mt][nt][hh*2+1] + __ldg(bp+f+1));
            }
        }
    }
}

// ---------------------------------------------------------------------------
extern "C" void kernel_launch(void* const* d_in, const int* in_sizes, int n_in,
                              void* d_out, int out_size)
{
    const float* x    = (const float*)d_in[0];
    const float* mask = (const float*)d_in[1];
    const float* Wqkv = (const float*)d_in[2];
    const float* Wp   = (const float*)d_in[3];
    const float* bp   = (const float*)d_in[4];
    const int*   ncp  = (n_in > 5) ? (const int*)d_in[5] : nullptr;

    cudaFuncSetAttribute(qkv_mma_kernel,
                         cudaFuncAttributeMaxDynamicSharedMemorySize, GEMM_SMEM_BYTES);
    cudaFuncSetAttribute(proj_mma_kernel,
                         cudaFuncAttributeMaxDynamicSharedMemorySize, GEMM_SMEM_BYTES);
    cudaFuncSetAttribute(attn_mma_kernel,
                         cudaFuncAttributeMaxDynamicSharedMemorySize, ATTN_SMEM_BYTES);

    round_pre      <<<4608, 256>>>(x, Wqkv, Wp);
    qkv_mma_kernel <<<dim3(F_/128, M_/128), 256, GEMM_SMEM_BYTES>>>(ncp);
    attn_mma_kernel<<<dim3(N_/128, B_*H_), 256, ATTN_SMEM_BYTES>>>(mask);
    proj_mma_kernel<<<dim3(C_/128, M_/128), 256, GEMM_SMEM_BYTES>>>(bp, (float*)d_out);
}

// round 6
// speedup vs baseline: 1.4211x; 1.1734x over previous
#include <cuda_runtime.h>
#include <math.h>
#include <stdint.h>

#define B_ 8
#define N_ 2048
#define C_ 512
#define H_ 8
#define D_ 64
#define F_ 1536
#define M_ (B_*N_)

// Scratch (allocation-free rule: __device__ globals), all pre-rounded tf32.
// g_xr/g_Wq/g_Wp/g_ctx/g_K have k-dim columns pair-permuted within 8-groups.
__device__ __align__(16) float g_Q[(size_t)B_*H_*N_*D_];
__device__ __align__(16) float g_K[(size_t)B_*H_*N_*D_];
__device__ __align__(16) float g_V[(size_t)B_*H_*N_*D_];
__device__ __align__(16) float g_ctx[(size_t)B_*N_*C_];
__device__ __align__(16) float g_xr[(size_t)M_*C_];
__device__ __align__(16) float g_Wq[(size_t)F_*C_];
__device__ __align__(16) float g_Wp[(size_t)C_*C_];
__device__ __align__(16) float g_rope[(size_t)N_*64];   // [pos][pair*2] = cos,sin

// ---------------------------------------------------------------------------
__device__ __forceinline__ float tf32r(float x) {
    float y;
    asm("cvt.rna.tf32.f32 %0, %1;" : "=f"(y) : "f"(x));
    return y;
}
// column permutation within 8-group: [0,4,1,5,2,6,3,7] -> pos(c) = 2*(c&3) | (c>>2)
__device__ __forceinline__ int perm8(int c) { return ((c & 3) << 1) | (c >> 2); }

__device__ __forceinline__ void mma_tf32(float* c, const uint32_t* a, const uint32_t* b) {
    asm volatile(
        "mma.sync.aligned.m16n8k8.row.col.f32.tf32.tf32.f32 "
        "{%0,%1,%2,%3},{%4,%5,%6,%7},{%8,%9},{%0,%1,%2,%3};\n"
        : "+f"(c[0]), "+f"(c[1]), "+f"(c[2]), "+f"(c[3])
        : "r"(a[0]), "r"(a[1]), "r"(a[2]), "r"(a[3]), "r"(b[0]), "r"(b[1]));
}
__device__ __forceinline__ void cpa16(uint32_t d, const float* s) {
    asm volatile("cp.async.cg.shared.global [%0], [%1], 16;" :: "r"(d), "l"(s));
}
__device__ __forceinline__ void cpa_commit() { asm volatile("cp.async.commit_group;"); }
#define CPA_WAIT0 asm volatile("cp.async.wait_group 0;")

// ---------------------------------------------------------------------------
// Kernel 0: tf32-round + pair-permute x/W_qkv/W_proj; build RoPE table.
// ---------------------------------------------------------------------------
#define X4_  (M_*C_/4)
#define WQ4_ (F_*C_/4)
#define WP4_ (C_*C_/4)
#define RT_  (N_*32)
__global__ __launch_bounds__(256) void round_pre(
    const float* __restrict__ x, const float* __restrict__ wq,
    const float* __restrict__ wp)
{
    int i = blockIdx.x * 256 + threadIdx.x;
    const int total = X4_ + WQ4_ + WP4_ + RT_;
    for (; i < total; i += gridDim.x * 256) {
        if (i < X4_ + WQ4_ + WP4_) {
            const float4* src; float* dst; int j;
            if (i < X4_)           { src = (const float4*)x;  dst = g_xr; j = i; }
            else if (i < X4_+WQ4_) { src = (const float4*)wq; dst = g_Wq; j = i - X4_; }
            else                   { src = (const float4*)wp; dst = g_Wp; j = i - X4_ - WQ4_; }
            float4 v = src[j];
            const int base = j * 4;
            float vv[4] = {v.x, v.y, v.z, v.w};
            #pragma unroll
            for (int u = 0; u < 4; u++) {
                const int c = base + u;
                dst[(c & ~7) | perm8(c & 7)] = tf32r(vv[u]);
            }
        } else {
            const int j = i - (X4_ + WQ4_ + WP4_);
            const int pos = j >> 5, pi = j & 31;
            const float invf = expf(-(float)pi * (9.210340371976184f/32.f));
            float sn, cs;
            sincosf((float)pos * invf, &sn, &cs);
            g_rope[(size_t)pos*64 + pi*2    ] = cs;
            g_rope[(size_t)pos*64 + pi*2 + 1] = sn;
        }
    }
}

// ---------------------------------------------------------------------------
// GEMM: CTA 128x128, k-chunk 32, 2-stage cp.async (issue-after-sync),
// row stride 40 floats (bank-shift 8 -> LDS.64 frags conflict-free).
// ---------------------------------------------------------------------------
#define GA 40
#define GTILE (128*GA)          // 5120
#define GSTG  (2*GTILE)         // 10240
#define GEMM_SMEM_BYTES (2*GSTG*4)   // 81920

__device__ __forceinline__ void gemm_issue(uint32_t smb, const float* A, const float* Bm,
                                           int m0, int f0, int lrow, int lcol, int kb, int st)
{
    const float* xa = A  + (size_t)(m0+lrow)*C_ + kb*32 + lcol;
    const float* wb = Bm + (size_t)(f0+lrow)*C_ + kb*32 + lcol;
    uint32_t da = smb + (uint32_t)(st*GSTG + lrow*GA + lcol)*4u;
    uint32_t db = da + GTILE*4u;
    #pragma unroll
    for (int p = 0; p < 4; p++) {
        cpa16(da + p*(32*GA*4), xa + (size_t)p*32*C_);
        cpa16(db + p*(32*GA*4), wb + (size_t)p*32*C_);
    }
    cpa_commit();
}

// inner compute on one 32-k chunk (stage base pointers As/Bs)
#define GEMM_CHUNK(As, Bs)                                                        \
    _Pragma("unroll")                                                             \
    for (int ks = 0; ks < 32; ks += 8) {                                          \
        uint32_t af[2][4];                                                        \
        _Pragma("unroll")                                                         \
        for (int mt = 0; mt < 2; mt++) {                                          \
            const float2 a0 = *(const float2*)((As) + (wm*32 + mt*16 + g    )*GA + ks + 2*tg); \
            const float2 a1 = *(const float2*)((As) + (wm*32 + mt*16 + g + 8)*GA + ks + 2*tg); \
            af[mt][0] = __float_as_uint(a0.x); af[mt][1] = __float_as_uint(a1.x); \
            af[mt][2] = __float_as_uint(a0.y); af[mt][3] = __float_as_uint(a1.y); \
        }                                                                         \
        uint32_t bf[8][2];                                                        \
        _Pragma("unroll")                                                         \
        for (int nt = 0; nt < 8; nt++) {                                          \
            const float2 b2 = *(const float2*)((Bs) + (wn*64 + nt*8 + g)*GA + ks + 2*tg); \
            bf[nt][0] = __float_as_uint(b2.x); bf[nt][1] = __float_as_uint(b2.y); \
        }                                                                         \
        _Pragma("unroll")                                                         \
        for (int mt = 0; mt < 2; mt++)                                            \
            _Pragma("unroll")                                                     \
            for (int nt = 0; nt < 8; nt++)                                        \
                mma_tf32(acc[mt][nt], af[mt], bf[nt]);                            \
    }

// Kernel 1: qkv = xr @ Wq^T, fused RoPE (+scale Q); K written pair-permuted.
__global__ __launch_bounds__(256, 2) void qkv_mma_kernel(const int* __restrict__ ncp)
{
    extern __shared__ float sm[];
    const uint32_t smb = (uint32_t)__cvta_generic_to_shared(sm);
    const int tid  = threadIdx.x;
    const int warp = tid >> 5, lane = tid & 31;
    const int g = lane >> 2, tg = lane & 3;
    const int wm = warp >> 1, wn = warp & 1;
    const int m0 = blockIdx.y * 128, f0 = blockIdx.x * 128;
    const int lrow = tid >> 3, lcol = (tid & 7) * 4;

    float acc[2][8][4] = {};
    gemm_issue(smb, g_xr, g_Wq, m0, f0, lrow, lcol, 0, 0);

    for (int kb = 0; kb < 16; kb++) {
        CPA_WAIT0;
        __syncthreads();
        if (kb < 15) gemm_issue(smb, g_xr, g_Wq, m0, f0, lrow, lcol, kb+1, (kb+1)&1);
        const float* As = sm + (kb&1)*GSTG;
        const float* Bs = As + GTILE;
        GEMM_CHUNK(As, Bs)
    }

    const int nc = ncp ? *ncp : 1;
    #pragma unroll
    for (int mt = 0; mt < 2; mt++) {
        #pragma unroll
        for (int hh = 0; hh < 2; hh++) {
            const int m = m0 + wm*32 + mt*16 + hh*8 + g;
            const int b = m >> 11, n = m & 2047;
            const int pos = n - nc;
            #pragma unroll
            for (int nt = 0; nt < 8; nt++) {
                const int f = f0 + wn*64 + nt*8 + 2*tg;
                float v0 = acc[mt][nt][hh*2+0], v1 = acc[mt][nt][hh*2+1];
                const int s = f >> 9, rem = f & 511, hd = rem >> 6, d0 = rem & 63;
                if (s < 2 && pos >= 0) {
                    const float2 cs = *(const float2*)&g_rope[(size_t)pos*64 + d0];
                    const float e = v0, o = v1;
                    v0 = e*cs.x - o*cs.y;
                    v1 = e*cs.y + o*cs.x;
                }
                v0 = tf32r(v0); v1 = tf32r(v1);
                if (s == 0) { v0 *= 0.125f; v1 *= 0.125f; }   // exact pow2
                const size_t base = (((size_t)b*H_ + hd)*N_ + n)*D_;
                if (s == 1) {       // K: pair-permuted d layout
                    g_K[base + ((d0 & ~7) | perm8(d0 & 7))]         = v0;
                    g_K[base + (((d0+1) & ~7) | perm8((d0+1) & 7))] = v1;
                } else {
                    float* dst = (s == 0) ? g_Q : g_V;
                    *(float2*)(dst + base + d0) = make_float2(v0, v1);
                }
            }
        }
    }
}

// Kernel 3: out = ctx @ Wp^T + b_proj
__global__ __launch_bounds__(256, 2) void proj_mma_kernel(
    const float* __restrict__ bp, float* __restrict__ out)
{
    extern __shared__ float sm[];
    const uint32_t smb = (uint32_t)__cvta_generic_to_shared(sm);
    const int tid  = threadIdx.x;
    const int warp = tid >> 5, lane = tid & 31;
    const int g = lane >> 2, tg = lane & 3;
    const int wm = warp >> 1, wn = warp & 1;
    const int m0 = blockIdx.y * 128, f0 = blockIdx.x * 128;
    const int lrow = tid >> 3, lcol = (tid & 7) * 4;

    float acc[2][8][4] = {};
    gemm_issue(smb, g_ctx, g_Wp, m0, f0, lrow, lcol, 0, 0);

    for (int kb = 0; kb < 16; kb++) {
        CPA_WAIT0;
        __syncthreads();
        if (kb < 15) gemm_issue(smb, g_ctx, g_Wp, m0, f0, lrow, lcol, kb+1, (kb+1)&1);
        const float* As = sm + (kb&1)*GSTG;
        const float* Bs = As + GTILE;
        GEMM_CHUNK(As, Bs)
    }

    #pragma unroll
    for (int mt = 0; mt < 2; mt++) {
        #pragma unroll
        for (int hh = 0; hh < 2; hh++) {
            const int m = m0 + wm*32 + mt*16 + hh*8 + g;
            #pragma unroll
            for (int nt = 0; nt < 8; nt++) {
                const int f = f0 + wn*64 + nt*8 + 2*tg;
                *(float2*)(out + (size_t)m*C_ + f) =
                    make_float2(acc[mt][nt][hh*2+0] + __ldg(bp+f),
                                acc[mt][nt][hh*2+1] + __ldg(bp+f+1));
            }
        }
    }
}

// ---------------------------------------------------------------------------
// Kernel 2: flash attention. CTA = 128 q x (b,h); warp = 16 q x 64 keys.
// 2-stage cp.async (issue-after-sync) -> 108.5KB smem -> 2 CTAs/SM.
// K tile pair-permuted (LDS.64 frags, stride 72). V natural (stride 72).
// Warp-local softmax; P via warp-private smem.
// ---------------------------------------------------------------------------
#define KTILE 4608            // 64*72
#define VTILE 4608            // 64*72
#define ASTG  (KTILE+VTILE)   // 9216
#define POFF  (2*ASTG)        // 18432
#define ATTN_SMEM_BYTES ((2*ASTG + 8*16*68)*4)   // 108544
#define NT_ (N_/64)

__device__ __forceinline__ void attn_issue(uint32_t smb, const float* Kg, const float* Vg,
                                           int lrow, int lc0, int t, int st)
{
    const float* ksrc = Kg + (size_t)t*64*D_ + (size_t)lrow*D_ + lc0;
    const float* vsrc = Vg + (size_t)t*64*D_ + (size_t)lrow*D_ + lc0;
    uint32_t kd = smb + (uint32_t)(st*ASTG + lrow*72 + lc0)*4u;
    uint32_t vd = smb + (uint32_t)(st*ASTG + KTILE + lrow*72 + lc0)*4u;
    #pragma unroll
    for (int u = 0; u < 4; u++) {
        cpa16(kd + u*16, ksrc + u*4);
        cpa16(vd + u*16, vsrc + u*4);
    }
    cpa_commit();
}

__global__ __launch_bounds__(256, 2) void attn_mma_kernel(const float* __restrict__ mask)
{
    extern __shared__ float sm[];
    const uint32_t smb = (uint32_t)__cvta_generic_to_shared(sm);
    const int tid  = threadIdx.x;
    const int warp = tid >> 5, lane = tid & 31;
    const int g = lane >> 2, tg = lane & 3;
    const int qb = blockIdx.x * 128;
    const int q0 = qb + warp * 16;
    const int bh = blockIdx.y, b = bh >> 3, h = bh & 7;
    const float* Qg = g_Q + (size_t)bh * N_ * D_;
    const float* Kg = g_K + (size_t)bh * N_ * D_;
    const float* Vg = g_V + (size_t)bh * N_ * D_;
    const float* mrow = mask + (size_t)b * N_;

    // Q A-frags resident (g_Q natural layout, tf32-rounded)
    uint32_t aq[8][4];
    #pragma unroll
    for (int ks = 0; ks < 8; ks++) {
        aq[ks][0] = __float_as_uint(Qg[(size_t)(q0+g  )*D_ + ks*8 + tg    ]);
        aq[ks][1] = __float_as_uint(Qg[(size_t)(q0+g+8)*D_ + ks*8 + tg    ]);
        aq[ks][2] = __float_as_uint(Qg[(size_t)(q0+g  )*D_ + ks*8 + tg + 4]);
        aq[ks][3] = __float_as_uint(Qg[(size_t)(q0+g+8)*D_ + ks*8 + tg + 4]);
    }

    const int lrow = tid >> 2, lc0 = (tid & 3) * 16;
    attn_issue(smb, Kg, Vg, lrow, lc0, 0, 0);

    float* Pw = sm + POFF + warp * (16*68);

    float O[8][4] = {};
    float rmax0 = -1e30f, rmax1 = -1e30f, rsum0 = 0.f, rsum1 = 0.f;

    for (int t = 0; t < NT_; t++) {
        CPA_WAIT0;
        __syncthreads();
        if (t + 1 < NT_) attn_issue(smb, Kg, Vg, lrow, lc0, t+1, (t+1)&1);

        const float* K_ = sm + (t&1)*ASTG;
        const float* V_ = K_ + KTILE;

        // ---- S = Q K^T (K pair-permuted -> one LDS.64 per B frag) ----
        float S[8][4] = {};
        #pragma unroll
        for (int ks = 0; ks < 8; ks++) {
            uint32_t bf[8][2];
            #pragma unroll
            for (int nt = 0; nt < 8; nt++) {
                const float2 b2 = *(const float2*)(K_ + (nt*8 + g)*72 + ks*8 + 2*tg);
                bf[nt][0] = __float_as_uint(b2.x);
                bf[nt][1] = __float_as_uint(b2.y);
            }
            #pragma unroll
            for (int nt = 0; nt < 8; nt++)
                mma_tf32(S[nt], aq[ks], bf[nt]);
        }

        // ---- + key mask; warp-local row max ----
        const int k0 = t*64;
        float tmax0 = -1e30f, tmax1 = -1e30f;
        #pragma unroll
        for (int nt = 0; nt < 8; nt++) {
            const float mv0 = __ldg(mrow + k0 + nt*8 + 2*tg);
            const float mv1 = __ldg(mrow + k0 + nt*8 + 2*tg + 1);
            S[nt][0] += mv0; S[nt][1] += mv1; S[nt][2] += mv0; S[nt][3] += mv1;
            tmax0 = fmaxf(tmax0, fmaxf(S[nt][0], S[nt][1]));
            tmax1 = fmaxf(tmax1, fmaxf(S[nt][2], S[nt][3]));
        }
        tmax0 = fmaxf(tmax0, __shfl_xor_sync(0xffffffffu, tmax0, 1));
        tmax0 = fmaxf(tmax0, __shfl_xor_sync(0xffffffffu, tmax0, 2));
        tmax1 = fmaxf(tmax1, __shfl_xor_sync(0xffffffffu, tmax1, 1));
        tmax1 = fmaxf(tmax1, __shfl_xor_sync(0xffffffffu, tmax1, 2));

        const float nm0 = fmaxf(rmax0, tmax0), nm1 = fmaxf(rmax1, tmax1);
        const float fac0 = __expf(rmax0 - nm0), fac1 = __expf(rmax1 - nm1);
        rmax0 = nm0; rmax1 = nm1;

        // ---- P = exp(S - m) -> warp-private smem (tf32); sums; O rescale ----
        float ts0 = 0.f, ts1 = 0.f;
        #pragma unroll
        for (int nt = 0; nt < 8; nt++) {
            const float p0 = __expf(S[nt][0] - nm0);
            const float p1 = __expf(S[nt][1] - nm0);
            const float p2 = __expf(S[nt][2] - nm1);
            const float p3 = __expf(S[nt][3] - nm1);
            ts0 += p0 + p1; ts1 += p2 + p3;
            *(float2*)&Pw[(g  )*68 + nt*8 + 2*tg] = make_float2(tf32r(p0), tf32r(p1));
            *(float2*)&Pw[(g+8)*68 + nt*8 + 2*tg] = make_float2(tf32r(p2), tf32r(p3));
            O[nt][0] *= fac0; O[nt][1] *= fac0; O[nt][2] *= fac1; O[nt][3] *= fac1;
        }
        ts0 += __shfl_xor_sync(0xffffffffu, ts0, 1);
        ts0 += __shfl_xor_sync(0xffffffffu, ts0, 2);
        ts1 += __shfl_xor_sync(0xffffffffu, ts1, 1);
        ts1 += __shfl_xor_sync(0xffffffffu, ts1, 2);
        rsum0 = rsum0*fac0 + ts0;
        rsum1 = rsum1*fac1 + ts1;
        __syncwarp();

        // ---- O += P V ----
        #pragma unroll
        for (int kc = 0; kc < 8; kc++) {
            uint32_t pa[4];
            pa[0] = __float_as_uint(Pw[(g  )*68 + kc*8 + tg    ]);
            pa[1] = __float_as_uint(Pw[(g+8)*68 + kc*8 + tg    ]);
            pa[2] = __float_as_uint(Pw[(g  )*68 + kc*8 + tg + 4]);
            pa[3] = __float_as_uint(Pw[(g+8)*68 + kc*8 + tg + 4]);
            uint32_t bf[8][2];
            #pragma unroll
            for (int nt = 0; nt < 8; nt++) {
                const float* vp2 = V_ + (kc*8 + tg)*72 + nt*8 + g;
                bf[nt][0]=__float_as_uint(vp2[0]);  bf[nt][1]=__float_as_uint(vp2[4*72]);
            }
            #pragma unroll
            for (int nt = 0; nt < 8; nt++)
                mma_tf32(O[nt], pa, bf[nt]);
        }
        __syncwarp();
    }

    // ---- normalize + write ctx [B, N, H*D], tf32 + pair-permuted for proj ----
    const float inv0 = 1.f / rsum0, inv1 = 1.f / rsum1;
    float* ctx0 = g_ctx + ((size_t)b*N_ + q0 + g    )*C_ + h*D_;
    float* ctx1 = g_ctx + ((size_t)b*N_ + q0 + g + 8)*C_ + h*D_;
    #pragma unroll
    for (int nt = 0; nt < 8; nt++) {
        const int d0 = nt*8 + 2*tg;
        const int p0 = (d0 & ~7) | perm8(d0 & 7);
        const int p1 = ((d0+1) & ~7) | perm8((d0+1) & 7);
        ctx0[p0] = tf32r(O[nt][0]*inv0);
        ctx0[p1] = tf32r(O[nt][1]*inv0);
        ctx1[p0] = tf32r(O[nt][2]*inv1);
        ctx1[p1] = tf32r(O[nt][3]*inv1);
    }
}

// ---------------------------------------------------------------------------
extern "C" void kernel_launch(void* const* d_in, const int* in_sizes, int n_in,
                              void* d_out, int out_size)
{
    const float* x    = (const float*)d_in[0];
    const float* mask = (const float*)d_in[1];
    const float* Wqkv = (const float*)d_in[2];
    const float* Wp   = (const float*)d_in[3];
    const float* bp   = (const float*)d_in[4];
    const int*   ncp  = (n_in > 5) ? (const int*)d_in[5] : nullptr;

    cudaFuncSetAttribute(qkv_mma_kernel,
                         cudaFuncAttributeMaxDynamicSharedMemorySize, GEMM_SMEM_BYTES);
    cudaFuncSetAttribute(proj_mma_kernel,
                         cudaFuncAttributeMaxDynamicSharedMemorySize, GEMM_SMEM_BYTES);
    cudaFuncSetAttribute(attn_mma_kernel,
                         cudaFuncAttributeMaxDynamicSharedMemorySize, ATTN_SMEM_BYTES);

    round_pre      <<<2048, 256>>>(x, Wqkv, Wp);
    qkv_mma_kernel <<<dim3(F_/128, M_/128), 256, GEMM_SMEM_BYTES>>>(ncp);
    attn_mma_kernel<<<dim3(N_/128, B_*H_), 256, ATTN_SMEM_BYTES>>>(mask);
    proj_mma_kernel<<<dim3(C_/128, M_/128), 256, GEMM_SMEM_BYTES>>>(bp, (float*)d_out);
}

// round 7
// speedup vs baseline: 1.4515x; 1.0214x over previous
#include <cuda_runtime.h>
#include <math.h>
#include <stdint.h>

#define B_ 8
#define N_ 2048
#define C_ 512
#define H_ 8
#define D_ 64
#define F_ 1536
#define M_ (B_*N_)

// Scratch (allocation-free rule: __device__ globals), all pre-rounded tf32.
// g_xr/g_Wq/g_Wp/g_ctx/g_K: k-dim pair-permuted within 8-groups.
// g_V: TRANSPOSED [B,H,D,N], key (N) dim pair-permuted within 8-groups.
__device__ __align__(16) float g_Q[(size_t)B_*H_*N_*D_];
__device__ __align__(16) float g_K[(size_t)B_*H_*N_*D_];
__device__ __align__(16) float g_V[(size_t)B_*H_*D_*N_];
__device__ __align__(16) float g_ctx[(size_t)B_*N_*C_];
__device__ __align__(16) float g_xr[(size_t)M_*C_];
__device__ __align__(16) float g_Wq[(size_t)F_*C_];
__device__ __align__(16) float g_Wp[(size_t)C_*C_];
__device__ __align__(16) float g_rope[(size_t)N_*64];   // [pos][pair*2] = cos,sin

// ---------------------------------------------------------------------------
__device__ __forceinline__ float tf32r(float x) {
    float y;
    asm("cvt.rna.tf32.f32 %0, %1;" : "=f"(y) : "f"(x));
    return y;
}
// position of element c within pair-permuted 8-group [0,4,1,5,2,6,3,7]
__device__ __forceinline__ int perm8(int c) { return ((c & 3) << 1) | (c >> 2); }

__device__ __forceinline__ void mma_tf32(float* c, const uint32_t* a, const uint32_t* b) {
    asm volatile(
        "mma.sync.aligned.m16n8k8.row.col.f32.tf32.tf32.f32 "
        "{%0,%1,%2,%3},{%4,%5,%6,%7},{%8,%9},{%0,%1,%2,%3};\n"
        : "+f"(c[0]), "+f"(c[1]), "+f"(c[2]), "+f"(c[3])
        : "r"(a[0]), "r"(a[1]), "r"(a[2]), "r"(a[3]), "r"(b[0]), "r"(b[1]));
}
__device__ __forceinline__ void cpa16(uint32_t d, const float* s) {
    asm volatile("cp.async.cg.shared.global [%0], [%1], 16;" :: "r"(d), "l"(s));
}
__device__ __forceinline__ void cpa_commit() { asm volatile("cp.async.commit_group;"); }
#define CPA_WAIT0 asm volatile("cp.async.wait_group 0;")

// ---------------------------------------------------------------------------
// Kernel 0: tf32-round + pair-permute x/W_qkv/W_proj; build RoPE table.
// ---------------------------------------------------------------------------
#define X4_  (M_*C_/4)
#define WQ4_ (F_*C_/4)
#define WP4_ (C_*C_/4)
#define RT_  (N_*32)
__global__ __launch_bounds__(256) void round_pre(
    const float* __restrict__ x, const float* __restrict__ wq,
    const float* __restrict__ wp)
{
    int i = blockIdx.x * 256 + threadIdx.x;
    const int total = X4_ + WQ4_ + WP4_ + RT_;
    for (; i < total; i += gridDim.x * 256) {
        if (i < X4_ + WQ4_ + WP4_) {
            const float4* src; float* dst; int j;
            if (i < X4_)           { src = (const float4*)x;  dst = g_xr; j = i; }
            else if (i < X4_+WQ4_) { src = (const float4*)wq; dst = g_Wq; j = i - X4_; }
            else                   { src = (const float4*)wp; dst = g_Wp; j = i - X4_ - WQ4_; }
            float4 v = src[j];
            const int base = j * 4;
            float vv[4] = {v.x, v.y, v.z, v.w};
            #pragma unroll
            for (int u = 0; u < 4; u++) {
                const int c = base + u;
                dst[(c & ~7) | perm8(c & 7)] = tf32r(vv[u]);
            }
        } else {
            const int j = i - (X4_ + WQ4_ + WP4_);
            const int pos = j >> 5, pi = j & 31;
            const float invf = expf(-(float)pi * (9.210340371976184f/32.f));
            float sn, cs;
            sincosf((float)pos * invf, &sn, &cs);
            g_rope[(size_t)pos*64 + pi*2    ] = cs;
            g_rope[(size_t)pos*64 + pi*2 + 1] = sn;
        }
    }
}

// ---------------------------------------------------------------------------
// GEMM: CTA 128x128, k-chunk 32, 2-stage cp.async (issue-after-sync),
// row stride 40 floats.
// ---------------------------------------------------------------------------
#define GA 40
#define GTILE (128*GA)
#define GSTG  (2*GTILE)
#define GEMM_SMEM_BYTES (2*GSTG*4)   // 81920

__device__ __forceinline__ void gemm_issue(uint32_t smb, const float* A, const float* Bm,
                                           int m0, int f0, int lrow, int lcol, int kb, int st)
{
    const float* xa = A  + (size_t)(m0+lrow)*C_ + kb*32 + lcol;
    const float* wb = Bm + (size_t)(f0+lrow)*C_ + kb*32 + lcol;
    uint32_t da = smb + (uint32_t)(st*GSTG + lrow*GA + lcol)*4u;
    uint32_t db = da + GTILE*4u;
    #pragma unroll
    for (int p = 0; p < 4; p++) {
        cpa16(da + p*(32*GA*4), xa + (size_t)p*32*C_);
        cpa16(db + p*(32*GA*4), wb + (size_t)p*32*C_);
    }
    cpa_commit();
}

#define GEMM_CHUNK(As, Bs)                                                        \
    _Pragma("unroll")                                                             \
    for (int ks = 0; ks < 32; ks += 8) {                                          \
        uint32_t af[2][4];                                                        \
        _Pragma("unroll")                                                         \
        for (int mt = 0; mt < 2; mt++) {                                          \
            const float2 a0 = *(const float2*)((As) + (wm*32 + mt*16 + g    )*GA + ks + 2*tg); \
            const float2 a1 = *(const float2*)((As) + (wm*32 + mt*16 + g + 8)*GA + ks + 2*tg); \
            af[mt][0] = __float_as_uint(a0.x); af[mt][1] = __float_as_uint(a1.x); \
            af[mt][2] = __float_as_uint(a0.y); af[mt][3] = __float_as_uint(a1.y); \
        }                                                                         \
        uint32_t bf[8][2];                                                        \
        _Pragma("unroll")                                                         \
        for (int nt = 0; nt < 8; nt++) {                                          \
            const float2 b2 = *(const float2*)((Bs) + (wn*64 + nt*8 + g)*GA + ks + 2*tg); \
            bf[nt][0] = __float_as_uint(b2.x); bf[nt][1] = __float_as_uint(b2.y); \
        }                                                                         \
        _Pragma("unroll")                                                         \
        for (int mt = 0; mt < 2; mt++)                                            \
            _Pragma("unroll")                                                     \
            for (int nt = 0; nt < 8; nt++)                                        \
                mma_tf32(acc[mt][nt], af[mt], bf[nt]);                            \
    }

// Kernel 1: qkv = xr @ Wq^T, fused RoPE (+scale Q).
// K written pair-permuted in d. V written TRANSPOSED [B,H,D,N], keys permuted.
__global__ __launch_bounds__(256, 2) void qkv_mma_kernel(const int* __restrict__ ncp)
{
    extern __shared__ float sm[];
    const uint32_t smb = (uint32_t)__cvta_generic_to_shared(sm);
    const int tid  = threadIdx.x;
    const int warp = tid >> 5, lane = tid & 31;
    const int g = lane >> 2, tg = lane & 3;
    const int wm = warp >> 1, wn = warp & 1;
    const int m0 = blockIdx.y * 128, f0 = blockIdx.x * 128;
    const int lrow = tid >> 3, lcol = (tid & 7) * 4;

    float acc[2][8][4] = {};
    gemm_issue(smb, g_xr, g_Wq, m0, f0, lrow, lcol, 0, 0);

    for (int kb = 0; kb < 16; kb++) {
        CPA_WAIT0;
        __syncthreads();
        if (kb < 15) gemm_issue(smb, g_xr, g_Wq, m0, f0, lrow, lcol, kb+1, (kb+1)&1);
        const float* As = sm + (kb&1)*GSTG;
        const float* Bs = As + GTILE;
        GEMM_CHUNK(As, Bs)
    }

    const int nc = ncp ? *ncp : 1;
    #pragma unroll
    for (int mt = 0; mt < 2; mt++) {
        #pragma unroll
        for (int hh = 0; hh < 2; hh++) {
            const int m = m0 + wm*32 + mt*16 + hh*8 + g;
            const int b = m >> 11, n = m & 2047;
            const int pos = n - nc;
            #pragma unroll
            for (int nt = 0; nt < 8; nt++) {
                const int f = f0 + wn*64 + nt*8 + 2*tg;
                float v0 = acc[mt][nt][hh*2+0], v1 = acc[mt][nt][hh*2+1];
                const int s = f >> 9, rem = f & 511, hd = rem >> 6, d0 = rem & 63;
                if (s < 2 && pos >= 0) {
                    const float2 cs = *(const float2*)&g_rope[(size_t)pos*64 + d0];
                    const float e = v0, o = v1;
                    v0 = e*cs.x - o*cs.y;
                    v1 = e*cs.y + o*cs.x;
                }
                v0 = tf32r(v0); v1 = tf32r(v1);
                if (s == 0) { v0 *= 0.125f; v1 *= 0.125f; }   // exact pow2
                const int bh = b*H_ + hd;
                if (s == 2) {          // V: [B,H,D,N], keys pair-permuted
                    const int pn = (n & ~7) | perm8(n & 7);
                    g_V[((size_t)bh*D_ + d0    )*N_ + pn] = v0;
                    g_V[((size_t)bh*D_ + d0 + 1)*N_ + pn] = v1;
                } else {
                    const size_t base = ((size_t)bh*N_ + n)*D_;
                    if (s == 1) {      // K: d pair-permuted
                        g_K[base + ((d0 & ~7) | perm8(d0 & 7))]         = v0;
                        g_K[base + (((d0+1) & ~7) | perm8((d0+1) & 7))] = v1;
                    } else {
                        *(float2*)(g_Q + base + d0) = make_float2(v0, v1);
                    }
                }
            }
        }
    }
}

// Kernel 3: out = ctx @ Wp^T + b_proj
__global__ __launch_bounds__(256, 2) void proj_mma_kernel(
    const float* __restrict__ bp, float* __restrict__ out)
{
    extern __shared__ float sm[];
    const uint32_t smb = (uint32_t)__cvta_generic_to_shared(sm);
    const int tid  = threadIdx.x;
    const int warp = tid >> 5, lane = tid & 31;
    const int g = lane >> 2, tg = lane & 3;
    const int wm = warp >> 1, wn = warp & 1;
    const int m0 = blockIdx.y * 128, f0 = blockIdx.x * 128;
    const int lrow = tid >> 3, lcol = (tid & 7) * 4;

    float acc[2][8][4] = {};
    gemm_issue(smb, g_ctx, g_Wp, m0, f0, lrow, lcol, 0, 0);

    for (int kb = 0; kb < 16; kb++) {
        CPA_WAIT0;
        __syncthreads();
        if (kb < 15) gemm_issue(smb, g_ctx, g_Wp, m0, f0, lrow, lcol, kb+1, (kb+1)&1);
        const float* As = sm + (kb&1)*GSTG;
        const float* Bs = As + GTILE;
        GEMM_CHUNK(As, Bs)
    }

    #pragma unroll
    for (int mt = 0; mt < 2; mt++) {
        #pragma unroll
        for (int hh = 0; hh < 2; hh++) {
            const int m = m0 + wm*32 + mt*16 + hh*8 + g;
            #pragma unroll
            for (int nt = 0; nt < 8; nt++) {
                const int f = f0 + wn*64 + nt*8 + 2*tg;
                *(float2*)(out + (size_t)m*C_ + f) =
                    make_float2(acc[mt][nt][hh*2+0] + __ldg(bp+f),
                                acc[mt][nt][hh*2+1] + __ldg(bp+f+1));
            }
        }
    }
}

// ---------------------------------------------------------------------------
// Kernel 2: flash attention. CTA = 128 q x (b,h); warp = 16 q x 64 keys.
// 2-stage cp.async; K tile [key][d-permuted] stride 72; V tile TRANSPOSED
// [d][key-permuted] stride 72. P stays in registers: exp in place on the S
// C-frags, intra-quad shuffle relayout to A-frags (verified in R3). No P smem
// -> 73.7KB smem, 2 CTAs/SM.
// ---------------------------------------------------------------------------
#define KTILE 4608            // 64*72
#define VTILE 4608            // 64*72
#define ASTG  (KTILE+VTILE)   // 9216
#define ATTN_SMEM_BYTES (2*ASTG*4)   // 73728
#define NT_ (N_/64)

__device__ __forceinline__ void attn_issue(uint32_t smb, const float* Kg, const float* Vg,
                                           int lrow, int lc0, int t, int st)
{
    const float* ksrc = Kg + (size_t)(t*64 + lrow)*D_ + lc0;       // K: [key][d]
    const float* vsrc = Vg + (size_t)lrow*N_ + t*64 + lc0;         // V: [d][key]
    uint32_t kd = smb + (uint32_t)(st*ASTG + lrow*72 + lc0)*4u;
    uint32_t vd = smb + (uint32_t)(st*ASTG + KTILE + lrow*72 + lc0)*4u;
    #pragma unroll
    for (int u = 0; u < 4; u++) {
        cpa16(kd + u*16, ksrc + u*4);
        cpa16(vd + u*16, vsrc + u*4);
    }
    cpa_commit();
}

__global__ __launch_bounds__(256, 2) void attn_mma_kernel(const float* __restrict__ mask)
{
    extern __shared__ float sm[];
    const uint32_t smb = (uint32_t)__cvta_generic_to_shared(sm);
    const int tid  = threadIdx.x;
    const int warp = tid >> 5, lane = tid & 31;
    const int g = lane >> 2, tg = lane & 3;
    const int qb = blockIdx.x * 128;
    const int q0 = qb + warp * 16;
    const int bh = blockIdx.y, b = bh >> 3;
    const float* Qg = g_Q + (size_t)bh * N_ * D_;
    const float* Kg = g_K + (size_t)bh * N_ * D_;
    const float* Vg = g_V + (size_t)bh * D_ * N_;
    const float* mrow = mask + (size_t)b * N_;

    // Q A-frags resident (g_Q natural layout, tf32-rounded)
    uint32_t aq[8][4];
    #pragma unroll
    for (int ks = 0; ks < 8; ks++) {
        aq[ks][0] = __float_as_uint(Qg[(size_t)(q0+g  )*D_ + ks*8 + tg    ]);
        aq[ks][1] = __float_as_uint(Qg[(size_t)(q0+g+8)*D_ + ks*8 + tg    ]);
        aq[ks][2] = __float_as_uint(Qg[(size_t)(q0+g  )*D_ + ks*8 + tg + 4]);
        aq[ks][3] = __float_as_uint(Qg[(size_t)(q0+g+8)*D_ + ks*8 + tg + 4]);
    }

    const int lrow = tid >> 2, lc0 = (tid & 3) * 16;
    attn_issue(smb, Kg, Vg, lrow, lc0, 0, 0);

    // shuffle relayout constants (C-frag -> A-frag, R3-verified)
    const int src1 = (lane & ~3) | (tg >> 1);
    const int src2 = src1 + 2;
    const bool oddc = (tg & 1);

    float O[8][4] = {};
    float rmax0 = -1e30f, rmax1 = -1e30f, rsum0 = 0.f, rsum1 = 0.f;

    for (int t = 0; t < NT_; t++) {
        CPA_WAIT0;
        __syncthreads();
        if (t + 1 < NT_) attn_issue(smb, Kg, Vg, lrow, lc0, t+1, (t+1)&1);

        const float* K_ = sm + (t&1)*ASTG;
        const float* V_ = K_ + KTILE;

        // ---- S = Q K^T ----
        float S[8][4] = {};
        #pragma unroll
        for (int ks = 0; ks < 8; ks++) {
            uint32_t bf[8][2];
            #pragma unroll
            for (int nt = 0; nt < 8; nt++) {
                const float2 b2 = *(const float2*)(K_ + (nt*8 + g)*72 + ks*8 + 2*tg);
                bf[nt][0] = __float_as_uint(b2.x);
                bf[nt][1] = __float_as_uint(b2.y);
            }
            #pragma unroll
            for (int nt = 0; nt < 8; nt++)
                mma_tf32(S[nt], aq[ks], bf[nt]);
        }

        // ---- + key mask; warp-local row max ----
        const int k0 = t*64;
        float tmax0 = -1e30f, tmax1 = -1e30f;
        #pragma unroll
        for (int nt = 0; nt < 8; nt++) {
            const float mv0 = __ldg(mrow + k0 + nt*8 + 2*tg);
            const float mv1 = __ldg(mrow + k0 + nt*8 + 2*tg + 1);
            S[nt][0] += mv0; S[nt][1] += mv1; S[nt][2] += mv0; S[nt][3] += mv1;
            tmax0 = fmaxf(tmax0, fmaxf(S[nt][0], S[nt][1]));
            tmax1 = fmaxf(tmax1, fmaxf(S[nt][2], S[nt][3]));
        }
        tmax0 = fmaxf(tmax0, __shfl_xor_sync(0xffffffffu, tmax0, 1));
        tmax0 = fmaxf(tmax0, __shfl_xor_sync(0xffffffffu, tmax0, 2));
        tmax1 = fmaxf(tmax1, __shfl_xor_sync(0xffffffffu, tmax1, 1));
        tmax1 = fmaxf(tmax1, __shfl_xor_sync(0xffffffffu, tmax1, 2));

        const float nm0 = fmaxf(rmax0, tmax0), nm1 = fmaxf(rmax1, tmax1);
        const float fac0 = __expf(rmax0 - nm0), fac1 = __expf(rmax1 - nm1);
        rmax0 = nm0; rmax1 = nm1;

        // ---- P = exp(S - m) in place (tf32); sums; O rescale ----
        float ts0 = 0.f, ts1 = 0.f;
        #pragma unroll
        for (int nt = 0; nt < 8; nt++) {
            const float p0 = __expf(S[nt][0] - nm0);
            const float p1 = __expf(S[nt][1] - nm0);
            const float p2 = __expf(S[nt][2] - nm1);
            const float p3 = __expf(S[nt][3] - nm1);
            ts0 += p0 + p1; ts1 += p2 + p3;
            S[nt][0] = tf32r(p0); S[nt][1] = tf32r(p1);
            S[nt][2] = tf32r(p2); S[nt][3] = tf32r(p3);
            O[nt][0] *= fac0; O[nt][1] *= fac0; O[nt][2] *= fac1; O[nt][3] *= fac1;
        }
        ts0 += __shfl_xor_sync(0xffffffffu, ts0, 1);
        ts0 += __shfl_xor_sync(0xffffffffu, ts0, 2);
        ts1 += __shfl_xor_sync(0xffffffffu, ts1, 1);
        ts1 += __shfl_xor_sync(0xffffffffu, ts1, 2);
        rsum0 = rsum0*fac0 + ts0;
        rsum1 = rsum1*fac1 + ts1;

        // ---- O += P V : shuffle C-frag -> A-frag; V^T LDS.64 B-frags ----
        #pragma unroll
        for (int kc = 0; kc < 8; kc++) {
            const uint32_t c0 = __float_as_uint(S[kc][0]);
            const uint32_t c1 = __float_as_uint(S[kc][1]);
            const uint32_t c2 = __float_as_uint(S[kc][2]);
            const uint32_t c3 = __float_as_uint(S[kc][3]);
            const uint32_t v00 = __shfl_sync(0xffffffffu, c0, src1);
            const uint32_t v01 = __shfl_sync(0xffffffffu, c1, src1);
            const uint32_t v10 = __shfl_sync(0xffffffffu, c2, src1);
            const uint32_t v11 = __shfl_sync(0xffffffffu, c3, src1);
            const uint32_t w00 = __shfl_sync(0xffffffffu, c0, src2);
            const uint32_t w01 = __shfl_sync(0xffffffffu, c1, src2);
            const uint32_t w10 = __shfl_sync(0xffffffffu, c2, src2);
            const uint32_t w11 = __shfl_sync(0xffffffffu, c3, src2);
            uint32_t pa[4];
            pa[0] = oddc ? v01 : v00;
            pa[1] = oddc ? v11 : v10;
            pa[2] = oddc ? w01 : w00;
            pa[3] = oddc ? w11 : w10;
            uint32_t bf[8][2];
            #pragma unroll
            for (int nt = 0; nt < 8; nt++) {
                const float2 vv = *(const float2*)(V_ + (nt*8 + g)*72 + kc*8 + 2*tg);
                bf[nt][0] = __float_as_uint(vv.x);
                bf[nt][1] = __float_as_uint(vv.y);
            }
            #pragma unroll
            for (int nt = 0; nt < 8; nt++)
                mma_tf32(O[nt], pa, bf[nt]);
        }
    }

    // ---- normalize + write ctx [B, N, H*D], tf32 + pair-permuted for proj ----
    const int h = bh & 7;
    const float inv0 = 1.f / rsum0, inv1 = 1.f / rsum1;
    float* ctx0 = g_ctx + ((size_t)b*N_ + q0 + g    )*C_ + h*D_;
    float* ctx1 = g_ctx + ((size_t)b*N_ + q0 + g + 8)*C_ + h*D_;
    #pragma unroll
    for (int nt = 0; nt < 8; nt++) {
        const int d0 = nt*8 + 2*tg;
        const int p0 = (d0 & ~7) | perm8(d0 & 7);
        const int p1 = ((d0+1) & ~7) | perm8((d0+1) & 7);
        ctx0[p0] = tf32r(O[nt][0]*inv0);
        ctx0[p1] = tf32r(O[nt][1]*inv0);
        ctx1[p0] = tf32r(O[nt][2]*inv1);
        ctx1[p1] = tf32r(O[nt][3]*inv1);
    }
}

// ---------------------------------------------------------------------------
extern "C" void kernel_launch(void* const* d_in, const int* in_sizes, int n_in,
                              void* d_out, int out_size)
{
    const float* x    = (const float*)d_in[0];
    const float* mask = (const float*)d_in[1];
    const float* Wqkv = (const float*)d_in[2];
    const float* Wp   = (const float*)d_in[3];
    const float* bp   = (const float*)d_in[4];
    const int*   ncp  = (n_in > 5) ? (const int*)d_in[5] : nullptr;

    cudaFuncSetAttribute(qkv_mma_kernel,
                         cudaFuncAttributeMaxDynamicSharedMemorySize, GEMM_SMEM_BYTES);
    cudaFuncSetAttribute(proj_mma_kernel,
                         cudaFuncAttributeMaxDynamicSharedMemorySize, GEMM_SMEM_BYTES);
    cudaFuncSetAttribute(attn_mma_kernel,
                         cudaFuncAttributeMaxDynamicSharedMemorySize, ATTN_SMEM_BYTES);

    round_pre      <<<2048, 256>>>(x, Wqkv, Wp);
    qkv_mma_kernel <<<dim3(F_/128, M_/128), 256, GEMM_SMEM_BYTES>>>(ncp);
    attn_mma_kernel<<<dim3(N_/128, B_*H_), 256, ATTN_SMEM_BYTES>>>(mask);
    proj_mma_kernel<<<dim3(C_/128, M_/128), 256, GEMM_SMEM_BYTES>>>(bp, (float*)d_out);
}

// round 8
// speedup vs baseline: 2.5252x; 1.7397x over previous
#include <cuda_runtime.h>
#include <cuda_fp16.h>
#include <math.h>
#include <stdint.h>

#define B_ 8
#define N_ 2048
#define C_ 512
#define H_ 8
#define D_ 64
#define F_ 1536
#define M_ (B_*N_)

// Scratch (allocation-free rule: __device__ globals), all fp16.
// All k-dims stored pair-of-pairs permuted within 16-groups:
// physical slot order [p0,p4,p1,p5,p2,p6,p3,p7] (pairs of halfs).
// g_V is TRANSPOSED [B,H,D,N] with the key dim permuted.
__device__ __align__(16) __half g_Q[(size_t)B_*H_*N_*D_];
__device__ __align__(16) __half g_K[(size_t)B_*H_*N_*D_];
__device__ __align__(16) __half g_V[(size_t)B_*H_*D_*N_];
__device__ __align__(16) __half g_ctx[(size_t)B_*N_*C_];
__device__ __align__(16) __half g_xr[(size_t)M_*C_];
__device__ __align__(16) __half g_Wq[(size_t)F_*C_];
__device__ __align__(16) __half g_Wp[(size_t)C_*C_];
__device__ __align__(16) float  g_rope[(size_t)N_*64];   // [pos][pair*2] = cos,sin

// ---------------------------------------------------------------------------
__device__ __forceinline__ int perm8(int q) { return ((q & 3) << 1) | (q >> 2); }
// permuted absolute index of element c (pair-preserving, within 16-groups)
__device__ __forceinline__ int pidx(int c) {
    return (c & ~15) | (perm8((c >> 1) & 7) << 1) | (c & 1);
}
__device__ __forceinline__ uint32_t h2pack(float a, float b) {
    __half2 h = __floats2half2_rn(a, b);
    return *(uint32_t*)&h;
}
__device__ __forceinline__ void mma_f16(float* c, const uint32_t* a, const uint32_t* b) {
    asm volatile(
        "mma.sync.aligned.m16n8k16.row.col.f32.f16.f16.f32 "
        "{%0,%1,%2,%3},{%4,%5,%6,%7},{%8,%9},{%0,%1,%2,%3};\n"
        : "+f"(c[0]), "+f"(c[1]), "+f"(c[2]), "+f"(c[3])
        : "r"(a[0]), "r"(a[1]), "r"(a[2]), "r"(a[3]), "r"(b[0]), "r"(b[1]));
}
__device__ __forceinline__ void cpa16(uint32_t d, const void* s) {
    asm volatile("cp.async.cg.shared.global [%0], [%1], 16;" :: "r"(d), "l"(s));
}
__device__ __forceinline__ void cpa_commit() { asm volatile("cp.async.commit_group;"); }
#define CPA_WAIT0 asm volatile("cp.async.wait_group 0;")

// ---------------------------------------------------------------------------
// Kernel 0: fp16-convert + permute x/W_qkv/W_proj; build RoPE table (fp32).
// ---------------------------------------------------------------------------
#define X4_  (M_*C_/4)
#define WQ4_ (F_*C_/4)
#define WP4_ (C_*C_/4)
#define RT_  (N_*32)
__global__ __launch_bounds__(256) void round_pre(
    const float* __restrict__ x, const float* __restrict__ wq,
    const float* __restrict__ wp)
{
    int i = blockIdx.x * 256 + threadIdx.x;
    const int total = X4_ + WQ4_ + WP4_ + RT_;
    for (; i < total; i += gridDim.x * 256) {
        if (i < X4_ + WQ4_ + WP4_) {
            const float4* src; __half* dst; int j;
            if (i < X4_)           { src = (const float4*)x;  dst = g_xr; j = i; }
            else if (i < X4_+WQ4_) { src = (const float4*)wq; dst = g_Wq; j = i - X4_; }
            else                   { src = (const float4*)wp; dst = g_Wp; j = i - X4_ - WQ4_; }
            float4 v = src[j];
            const int c = j * 4;
            *(__half2*)(dst + pidx(c))     = __floats2half2_rn(v.x, v.y);
            *(__half2*)(dst + pidx(c + 2)) = __floats2half2_rn(v.z, v.w);
        } else {
            const int j = i - (X4_ + WQ4_ + WP4_);
            const int pos = j >> 5, pi = j & 31;
            const float invf = expf(-(float)pi * (9.210340371976184f/32.f));
            float sn, cs;
            sincosf((float)pos * invf, &sn, &cs);
            g_rope[(size_t)pos*64 + pi*2    ] = cs;
            g_rope[(size_t)pos*64 + pi*2 + 1] = sn;
        }
    }
}

// ---------------------------------------------------------------------------
// GEMM: CTA 128x128, k-chunk 32 halfs, 2-stage cp.async (issue-after-sync).
// Smem row stride 48 halfs (96B): phase-conflict-free for 8B fragment loads.
// ---------------------------------------------------------------------------
#define GA 48
#define GTILEH (128*GA)          // 6144 halfs per tile
#define GSTGH  (2*GTILEH)        // A+B per stage
#define GEMM_SMEM_BYTES (2*GSTGH*2)   // 49152

__device__ __forceinline__ void gemm_issue(uint32_t smb, const __half* A, const __half* Bm,
                                           int m0, int f0, int lrow, int lhc, int kb, int st)
{
    const __half* xa = A  + (size_t)(m0+lrow)*C_ + kb*32 + lhc;
    const __half* wb = Bm + (size_t)(f0+lrow)*C_ + kb*32 + lhc;
    uint32_t da = smb + (uint32_t)st*(GSTGH*2) + (uint32_t)(lrow*GA + lhc)*2u;
    uint32_t db = da + GTILEH*2u;
    cpa16(da,      xa);
    cpa16(da + 16, xa + 8);
    cpa16(db,      wb);
    cpa16(db + 16, wb + 8);
    cpa_commit();
}

#define GEMM_CHUNK(As, Bs)                                                        \
    _Pragma("unroll")                                                             \
    for (int ks = 0; ks < 2; ks++) {                                              \
        uint32_t af[2][4];                                                        \
        _Pragma("unroll")                                                         \
        for (int mt = 0; mt < 2; mt++) {                                          \
            const uint2 a0 = *(const uint2*)((As) + (wm*32 + mt*16 + g    )*GA + ks*16 + 4*tg); \
            const uint2 a1 = *(const uint2*)((As) + (wm*32 + mt*16 + g + 8)*GA + ks*16 + 4*tg); \
            af[mt][0] = a0.x; af[mt][2] = a0.y;                                   \
            af[mt][1] = a1.x; af[mt][3] = a1.y;                                   \
        }                                                                         \
        uint32_t bf[8][2];                                                        \
        _Pragma("unroll")                                                         \
        for (int nt = 0; nt < 8; nt++) {                                          \
            const uint2 b2 = *(const uint2*)((Bs) + (wn*64 + nt*8 + g)*GA + ks*16 + 4*tg); \
            bf[nt][0] = b2.x; bf[nt][1] = b2.y;                                   \
        }                                                                         \
        _Pragma("unroll")                                                         \
        for (int mt = 0; mt < 2; mt++)                                            \
            _Pragma("unroll")                                                     \
            for (int nt = 0; nt < 8; nt++)                                        \
                mma_f16(acc[mt][nt], af[mt], bf[nt]);                             \
    }

// Kernel 1: qkv = xr @ Wq^T, fused RoPE (+scale Q); Q/K permuted-d, V transposed.
__global__ __launch_bounds__(256, 2) void qkv_mma_kernel(const int* __restrict__ ncp)
{
    extern __shared__ __half smh[];
    const uint32_t smb = (uint32_t)__cvta_generic_to_shared(smh);
    const int tid  = threadIdx.x;
    const int warp = tid >> 5, lane = tid & 31;
    const int g = lane >> 2, tg = lane & 3;
    const int wm = warp >> 1, wn = warp & 1;
    const int m0 = blockIdx.y * 128, f0 = blockIdx.x * 128;
    const int lrow = tid >> 1, lhc = (tid & 1) * 16;

    float acc[2][8][4] = {};
    gemm_issue(smb, g_xr, g_Wq, m0, f0, lrow, lhc, 0, 0);

    for (int kb = 0; kb < 16; kb++) {
        CPA_WAIT0;
        __syncthreads();
        if (kb < 15) gemm_issue(smb, g_xr, g_Wq, m0, f0, lrow, lhc, kb+1, (kb+1)&1);
        const __half* As = smh + (kb&1)*GSTGH;
        const __half* Bs = As + GTILEH;
        GEMM_CHUNK(As, Bs)
    }

    const int nc = ncp ? *ncp : 1;
    #pragma unroll
    for (int mt = 0; mt < 2; mt++) {
        #pragma unroll
        for (int hh = 0; hh < 2; hh++) {
            const int m = m0 + wm*32 + mt*16 + hh*8 + g;
            const int b = m >> 11, n = m & 2047;
            const int pos = n - nc;
            #pragma unroll
            for (int nt = 0; nt < 8; nt++) {
                const int f = f0 + wn*64 + nt*8 + 2*tg;
                float v0 = acc[mt][nt][hh*2+0], v1 = acc[mt][nt][hh*2+1];
                const int s = f >> 9, rem = f & 511, hd = rem >> 6, d0 = rem & 63;
                if (s < 2 && pos >= 0) {
                    const float2 cs = *(const float2*)&g_rope[(size_t)pos*64 + d0];
                    const float e = v0, o = v1;
                    v0 = e*cs.x - o*cs.y;
                    v1 = e*cs.y + o*cs.x;
                }
                if (s == 0) { v0 *= 0.125f; v1 *= 0.125f; }   // exact pow2
                const int bh = b*H_ + hd;
                if (s == 2) {          // V: [B,H,D,N], keys permuted
                    const int pn = pidx(n & 15) + (n & ~15);
                    g_V[((size_t)bh*D_ + d0    )*N_ + pn] = __float2half(v0);
                    g_V[((size_t)bh*D_ + d0 + 1)*N_ + pn] = __float2half(v1);
                } else {               // Q/K: d permuted, half2 store
                    const size_t base = ((size_t)bh*N_ + n)*D_;
                    __half* dst = (s == 1) ? g_K : g_Q;
                    *(__half2*)(dst + base + pidx(d0)) = __floats2half2_rn(v0, v1);
                }
            }
        }
    }
}

// Kernel 3: out = ctx @ Wp^T + b_proj (fp32 out)
__global__ __launch_bounds__(256, 2) void proj_mma_kernel(
    const float* __restrict__ bp, float* __restrict__ out)
{
    extern __shared__ __half smh[];
    const uint32_t smb = (uint32_t)__cvta_generic_to_shared(smh);
    const int tid  = threadIdx.x;
    const int warp = tid >> 5, lane = tid & 31;
    const int g = lane >> 2, tg = lane & 3;
    const int wm = warp >> 1, wn = warp & 1;
    const int m0 = blockIdx.y * 128, f0 = blockIdx.x * 128;
    const int lrow = tid >> 1, lhc = (tid & 1) * 16;

    float acc[2][8][4] = {};
    gemm_issue(smb, g_ctx, g_Wp, m0, f0, lrow, lhc, 0, 0);

    for (int kb = 0; kb < 16; kb++) {
        CPA_WAIT0;
        __syncthreads();
        if (kb < 15) gemm_issue(smb, g_ctx, g_Wp, m0, f0, lrow, lhc, kb+1, (kb+1)&1);
        const __half* As = smh + (kb&1)*GSTGH;
        const __half* Bs = As + GTILEH;
        GEMM_CHUNK(As, Bs)
    }

    #pragma unroll
    for (int mt = 0; mt < 2; mt++) {
        #pragma unroll
        for (int hh = 0; hh < 2; hh++) {
            const int m = m0 + wm*32 + mt*16 + hh*8 + g;
            #pragma unroll
            for (int nt = 0; nt < 8; nt++) {
                const int f = f0 + wn*64 + nt*8 + 2*tg;
                *(float2*)(out + (size_t)m*C_ + f) =
                    make_float2(acc[mt][nt][hh*2+0] + __ldg(bp+f),
                                acc[mt][nt][hh*2+1] + __ldg(bp+f+1));
            }
        }
    }
}

// ---------------------------------------------------------------------------
// Kernel 2: flash attention, fp16 mma. CTA = 128 q x (b,h); warp = 16 q x 64 k.
// K tile [key][d-perm] stride 80; V^T tile [d][key-perm] stride 80.
// P C-frags pack DIRECTLY into fp16 A-frags (layout identity) — no shuffles,
// no P smem. 2-stage cp.async, 40KB smem, 2 CTAs/SM.
// ---------------------------------------------------------------------------
#define KROW 80
#define KTILEH (64*KROW)         // 5120 halfs
#define ASTGH  (2*KTILEH)        // 10240 halfs per stage (K+V)
#define ATTN_SMEM_BYTES (2*ASTGH*2)   // 40960
#define NT_ (N_/64)

__device__ __forceinline__ void attn_issue(uint32_t smb, const __half* Kg, const __half* Vg,
                                           int lrow, int lhc, int t, int st)
{
    const __half* ksrc = Kg + (size_t)(t*64 + lrow)*D_ + lhc;   // K: [key][d-perm]
    const __half* vsrc = Vg + (size_t)lrow*N_ + t*64 + lhc;     // V: [d][key-perm]
    uint32_t kd = smb + (uint32_t)st*(ASTGH*2) + (uint32_t)(lrow*KROW + lhc)*2u;
    uint32_t vd = kd + KTILEH*2u;
    cpa16(kd,      ksrc);
    cpa16(kd + 16, ksrc + 8);
    cpa16(vd,      vsrc);
    cpa16(vd + 16, vsrc + 8);
    cpa_commit();
}

__global__ __launch_bounds__(256, 2) void attn_mma_kernel(const float* __restrict__ mask)
{
    extern __shared__ __half smh[];
    const uint32_t smb = (uint32_t)__cvta_generic_to_shared(smh);
    const int tid  = threadIdx.x;
    const int warp = tid >> 5, lane = tid & 31;
    const int g = lane >> 2, tg = lane & 3;
    const int qb = blockIdx.x * 128;
    const int q0 = qb + warp * 16;
    const int bh = blockIdx.y, b = bh >> 3;
    const __half* Qg = g_Q + (size_t)bh * N_ * D_;
    const __half* Kg = g_K + (size_t)bh * N_ * D_;
    const __half* Vg = g_V + (size_t)bh * D_ * N_;
    const float* mrow = mask + (size_t)b * N_;

    // Q A-frags resident: per k16 step, one uint2 per row (permuted layout)
    uint32_t aq[4][4];
    #pragma unroll
    for (int ks = 0; ks < 4; ks++) {
        const uint2 q1 = *(const uint2*)(Qg + (size_t)(q0+g  )*D_ + ks*16 + 4*tg);
        const uint2 q2 = *(const uint2*)(Qg + (size_t)(q0+g+8)*D_ + ks*16 + 4*tg);
        aq[ks][0] = q1.x; aq[ks][2] = q1.y;
        aq[ks][1] = q2.x; aq[ks][3] = q2.y;
    }

    const int lrow = tid >> 2, lhc = (tid & 3) * 16;
    attn_issue(smb, Kg, Vg, lrow, lhc, 0, 0);

    float O[8][4] = {};
    float rmax0 = -1e30f, rmax1 = -1e30f, rsum0 = 0.f, rsum1 = 0.f;

    for (int t = 0; t < NT_; t++) {
        CPA_WAIT0;
        __syncthreads();
        if (t + 1 < NT_) attn_issue(smb, Kg, Vg, lrow, lhc, t+1, (t+1)&1);

        const __half* K_ = smh + (t&1)*ASTGH;
        const __half* V_ = K_ + KTILEH;

        // ---- S = Q K^T : 4 k16 steps x 8 n-tiles ----
        float S[8][4] = {};
        #pragma unroll
        for (int ks = 0; ks < 4; ks++) {
            uint32_t bf[8][2];
            #pragma unroll
            for (int nt = 0; nt < 8; nt++) {
                const uint2 b2 = *(const uint2*)(K_ + (nt*8 + g)*KROW + ks*16 + 4*tg);
                bf[nt][0] = b2.x; bf[nt][1] = b2.y;
            }
            #pragma unroll
            for (int nt = 0; nt < 8; nt++)
                mma_f16(S[nt], aq[ks], bf[nt]);
        }

        // ---- + key mask; warp-local row max ----
        const int k0 = t*64;
        float tmax0 = -1e30f, tmax1 = -1e30f;
        #pragma unroll
        for (int nt = 0; nt < 8; nt++) {
            const float mv0 = __ldg(mrow + k0 + nt*8 + 2*tg);
            const float mv1 = __ldg(mrow + k0 + nt*8 + 2*tg + 1);
            S[nt][0] += mv0; S[nt][1] += mv1; S[nt][2] += mv0; S[nt][3] += mv1;
            tmax0 = fmaxf(tmax0, fmaxf(S[nt][0], S[nt][1]));
            tmax1 = fmaxf(tmax1, fmaxf(S[nt][2], S[nt][3]));
        }
        tmax0 = fmaxf(tmax0, __shfl_xor_sync(0xffffffffu, tmax0, 1));
        tmax0 = fmaxf(tmax0, __shfl_xor_sync(0xffffffffu, tmax0, 2));
        tmax1 = fmaxf(tmax1, __shfl_xor_sync(0xffffffffu, tmax1, 1));
        tmax1 = fmaxf(tmax1, __shfl_xor_sync(0xffffffffu, tmax1, 2));

        const float nm0 = fmaxf(rmax0, tmax0), nm1 = fmaxf(rmax1, tmax1);
        const float fac0 = __expf(rmax0 - nm0), fac1 = __expf(rmax1 - nm1);
        rmax0 = nm0; rmax1 = nm1;

        // ---- P = exp(S-m): pack C-frags directly into fp16 A-frags ----
        uint32_t pa[4][4];
        float ts0 = 0.f, ts1 = 0.f;
        #pragma unroll
        for (int nt = 0; nt < 8; nt++) {
            const float p0 = __expf(S[nt][0] - nm0);
            const float p1 = __expf(S[nt][1] - nm0);
            const float p2 = __expf(S[nt][2] - nm1);
            const float p3 = __expf(S[nt][3] - nm1);
            ts0 += p0 + p1; ts1 += p2 + p3;
            const int kc = nt >> 1;
            if (nt & 1) { pa[kc][2] = h2pack(p0, p1); pa[kc][3] = h2pack(p2, p3); }
            else        { pa[kc][0] = h2pack(p0, p1); pa[kc][1] = h2pack(p2, p3); }
            O[nt][0] *= fac0; O[nt][1] *= fac0; O[nt][2] *= fac1; O[nt][3] *= fac1;
        }
        ts0 += __shfl_xor_sync(0xffffffffu, ts0, 1);
        ts0 += __shfl_xor_sync(0xffffffffu, ts0, 2);
        ts1 += __shfl_xor_sync(0xffffffffu, ts1, 1);
        ts1 += __shfl_xor_sync(0xffffffffu, ts1, 2);
        rsum0 = rsum0*fac0 + ts0;
        rsum1 = rsum1*fac1 + ts1;

        // ---- O += P V : 4 k16 steps over keys; V^T LDS.64 B-frags ----
        #pragma unroll
        for (int kc = 0; kc < 4; kc++) {
            uint32_t bf[8][2];
            #pragma unroll
            for (int nt = 0; nt < 8; nt++) {
                const uint2 vv = *(const uint2*)(V_ + (nt*8 + g)*KROW + kc*16 + 4*tg);
                bf[nt][0] = vv.x; bf[nt][1] = vv.y;
            }
            #pragma unroll
            for (int nt = 0; nt < 8; nt++)
                mma_f16(O[nt], pa[kc], bf[nt]);
        }
    }

    // ---- normalize + write ctx [B, N, H*D] fp16, C-dim permuted ----
    const int h = bh & 7;
    const float inv0 = 1.f / rsum0, inv1 = 1.f / rsum1;
    __half* ctx0 = g_ctx + ((size_t)b*N_ + q0 + g    )*C_ + h*D_;
    __half* ctx1 = g_ctx + ((size_t)b*N_ + q0 + g + 8)*C_ + h*D_;
    #pragma unroll
    for (int nt = 0; nt < 8; nt++) {
        const int d0 = nt*8 + 2*tg;
        const int pd = pidx(d0);
        *(__half2*)(ctx0 + pd) = __floats2half2_rn(O[nt][0]*inv0, O[nt][1]*inv0);
        *(__half2*)(ctx1 + pd) = __floats2half2_rn(O[nt][2]*inv1, O[nt][3]*inv1);
    }
}

// ---------------------------------------------------------------------------
extern "C" void kernel_launch(void* const* d_in, const int* in_sizes, int n_in,
                              void* d_out, int out_size)
{
    const float* x    = (const float*)d_in[0];
    const float* mask = (const float*)d_in[1];
    const float* Wqkv = (const float*)d_in[2];
    const float* Wp   = (const float*)d_in[3];
    const float* bp   = (const float*)d_in[4];
    const int*   ncp  = (n_in > 5) ? (const int*)d_in[5] : nullptr;

    cudaFuncSetAttribute(qkv_mma_kernel,
                         cudaFuncAttributeMaxDynamicSharedMemorySize, GEMM_SMEM_BYTES);
    cudaFuncSetAttribute(proj_mma_kernel,
                         cudaFuncAttributeMaxDynamicSharedMemorySize, GEMM_SMEM_BYTES);
    cudaFuncSetAttribute(attn_mma_kernel,
                         cudaFuncAttributeMaxDynamicSharedMemorySize, ATTN_SMEM_BYTES);

    round_pre      <<<2048, 256>>>(x, Wqkv, Wp);
    qkv_mma_kernel <<<dim3(F_/128, M_/128), 256, GEMM_SMEM_BYTES>>>(ncp);
    attn_mma_kernel<<<dim3(N_/128, B_*H_), 256, ATTN_SMEM_BYTES>>>(mask);
    proj_mma_kernel<<<dim3(C_/128, M_/128), 256, GEMM_SMEM_BYTES>>>(bp, (float*)d_out);
}